// round 7
// baseline (speedup 1.0000x reference)
#include <cuda_runtime.h>
#include <cuda_fp16.h>
#include <math.h>
#include <stdint.h>

#define B_  32
#define L_  512
#define SD_ 17
#define AD_ 6
#define DM_ 384
#define NL_ 12
#define N2_ 32
#define LT_ 2048           // 4*L
#define EPS_ 1e-5f

typedef unsigned long long u64;

// ---------------- scratch (device globals; no allocations allowed) -------------
__device__ float  g_z  [B_*DM_*LT_];    // embed output (layer-0 input)
__device__ float  g_zt [B_*DM_*LT_];    // raw residual stream (pre-LN), in-place
__device__ __half g_xh [B_*DM_*LT_];    // gelu output, fp16 hi
__device__ __half g_xl [B_*DM_*LT_];    // gelu output, fp16 lo
__device__ __half g_wh [NL_*768*DM_];   // conv_w fp16 hi
__device__ __half g_wl [NL_*768*DM_];   // conv_w fp16 lo
__device__ float2 g_lam[NL_*DM_*N2_];
__device__ float2 g_cm [NL_*DM_*N2_];
__device__ float  g_sum[B_*LT_];        // LN partial sums (zeroed by k_statfin)
__device__ float  g_sq [B_*LT_];
__device__ float  g_m  [B_*LT_];        // LN mean
__device__ float  g_r  [B_*LT_];        // LN rstd

__device__ __forceinline__ uint32_t smem_u32(const void* p) {
    uint32_t a;
    asm("{ .reg .u64 t; cvta.to.shared.u64 t, %1; cvt.u32.u64 %0, t; }" : "=r"(a) : "l"(p));
    return a;
}
__device__ __forceinline__ void cpa16(uint32_t dst, const void* src) {
    asm volatile("cp.async.cg.shared.global [%0], [%1], 16;" :: "r"(dst), "l"(src) : "memory");
}
// ---- packed f32x2 helpers ----
__device__ __forceinline__ u64 pk2(float x, float y) {
    u64 r; asm("mov.b64 %0, {%1,%2};" : "=l"(r) : "f"(x), "f"(y)); return r;
}
__device__ __forceinline__ void upk2(u64 v, float& x, float& y) {
    asm("mov.b64 {%0,%1}, %2;" : "=f"(x), "=f"(y) : "l"(v));
}
__device__ __forceinline__ u64 fma2_(u64 a, u64 b, u64 c) {
    u64 d; asm("fma.rn.f32x2 %0, %1, %2, %3;" : "=l"(d) : "l"(a), "l"(b), "l"(c)); return d;
}
__device__ __forceinline__ u64 mul2_(u64 a, u64 b) {
    u64 d; asm("mul.rn.f32x2 %0, %1, %2;" : "=l"(d) : "l"(a), "l"(b)); return d;
}
__device__ __forceinline__ u64 add2_(u64 a, u64 b) {
    u64 d; asm("add.rn.f32x2 %0, %1, %2;" : "=l"(d) : "l"(a), "l"(b)); return d;
}

// ---------------- K0: per-layer S4D coefficient precompute ---------------------
__global__ void k_precompute(const float* __restrict__ log_dt,
                             const float* __restrict__ C_ri,
                             const float* __restrict__ log_A_real,
                             const float* __restrict__ A_imag) {
    int idx = blockIdx.x * blockDim.x + threadIdx.x;
    if (idx >= NL_*DM_*N2_) return;
    int h = (idx / N2_) % DM_;
    int i = idx / (N2_*DM_);
    float dt = expf(log_dt[i*DM_ + h]);
    float Ar = -expf(log_A_real[idx]);
    float Ai = A_imag[idx];
    float dr = Ar*dt, di = Ai*dt;
    float er = expf(dr);
    float lr = er*cosf(di), li = er*sinf(di);
    float exr = lr - 1.0f, exi = li;
    float den = Ar*Ar + Ai*Ai;
    float wr = (exr*Ar + exi*Ai)/den;
    float wi = (exi*Ar - exr*Ai)/den;
    float Cr = C_ri[idx*2+0], Ci = C_ri[idx*2+1];
    g_lam[idx] = make_float2(lr, li);
    g_cm[idx]  = make_float2(2.0f*(Cr*wr - Ci*wi), 2.0f*(Cr*wi + Ci*wr));
}

// ---------------- K0b: weight split fp32 -> fp16 hi/lo -------------------------
__global__ void k_prep_w(const float* __restrict__ conv_w) {
    int idx = blockIdx.x * blockDim.x + threadIdx.x;
    if (idx >= NL_*768*DM_) return;
    float v = conv_w[idx];
    __half h = __float2half_rn(v);
    g_wh[idx] = h;
    g_wl[idx] = __float2half_rn(v - __half2float(h));
}

// ---------------- K1: embedding + interleave into (B, DM, 4L) ------------------
__global__ void k_embed(const float* __restrict__ states,
                        const float* __restrict__ actions,
                        const float* __restrict__ rtg,
                        const float* __restrict__ ctg,
                        const int*   __restrict__ tsteps,
                        const float* __restrict__ W_es, const float* __restrict__ b_es,
                        const float* __restrict__ W_ea, const float* __restrict__ b_ea,
                        const float* __restrict__ W_er, const float* __restrict__ b_er,
                        const float* __restrict__ W_ec, const float* __restrict__ b_ec,
                        const float* __restrict__ E_t) {
    int bl = blockIdx.x;
    int b = bl / L_, l = bl % L_;
    int h = threadIdx.x;
    int t = tsteps[bl];
    float te = E_t[t*DM_ + h];
    float r = rtg[bl], c = ctg[bl];
    float er = fmaf(r, W_er[h], b_er[h]) + te;
    float ec = fmaf(c, W_ec[h], b_ec[h]) + te;
    float es = b_es[h] + te;
    #pragma unroll
    for (int s = 0; s < SD_; s++) es = fmaf(states[bl*SD_ + s], W_es[s*DM_ + h], es);
    float ea = b_ea[h] + te;
    #pragma unroll
    for (int s = 0; s < AD_; s++) ea = fmaf(actions[bl*AD_ + s], W_ea[s*DM_ + h], ea);
    float* zr = g_z + ((size_t)(b*DM_ + h))*LT_ + 4*l;
    zr[0] = er; zr[1] = ec; zr[2] = es; zr[3] = ea;
}

// ---------------- K2: S4D recurrence, 2 batch-streams/lane via f32x2 -----------
// 16-step transpose buffer (half smem -> 2x occupancy); half-warp column reduce
// + one 64-bit shfl_xor(16) to combine halves.
__global__ __launch_bounds__(128) void k_s4d(const float* __restrict__ Dskip,
                                             const float* __restrict__ ln_g,
                                             const float* __restrict__ ln_b,
                                             int layer, int prev) {
    __shared__ u64 buf[4][32][17];
    __shared__ u64 zs [4][32];
    int wid  = threadIdx.x >> 5;
    int lane = threadIdx.x & 31;
    int gw = blockIdx.x*4 + wid;
    int h  = gw % DM_;
    int bq = gw / DM_;
    int b0 = bq*2, b1 = bq*2 + 1;
    int pidx = (layer*DM_ + h)*N2_ + lane;
    float2 LM = g_lam[pidx];
    float2 CM = g_cm[pidx];
    u64 LMx2  = pk2( LM.x,  LM.x);
    u64 LMy2  = pk2( LM.y,  LM.y);
    u64 nLMy2 = pk2(-LM.y, -LM.y);
    u64 CMx2  = pk2( CM.x,  CM.x);
    u64 nCMy2 = pk2(-CM.y, -CM.y);
    float D   = Dskip[layer*DM_ + h];
    float lng = 1.0f, lnb = 0.0f;
    const float* zsrc = prev ? g_zt : g_z;
    if (prev) { lng = ln_g[(layer-1)*DM_ + h]; lnb = ln_b[(layer-1)*DM_ + h]; }
    const float* z0r = zsrc + ((size_t)(b0*DM_ + h))*LT_;
    const float* z1r = zsrc + ((size_t)(b1*DM_ + h))*LT_;
    const float* m0r = g_m + (size_t)b0*LT_;
    const float* m1r = g_m + (size_t)b1*LT_;
    const float* r0r = g_r + (size_t)b0*LT_;
    const float* r1r = g_r + (size_t)b1*LT_;
    __half* xh0 = g_xh + ((size_t)(b0*DM_ + h))*LT_;
    __half* xl0 = g_xl + ((size_t)(b0*DM_ + h))*LT_;
    __half* xh1 = g_xh + ((size_t)(b1*DM_ + h))*LT_;
    __half* xl1 = g_xl + ((size_t)(b1*DM_ + h))*LT_;

    u64 sr = 0ULL, si = 0ULL;
    u64 (*bw)[17] = buf[wid];
    u64* zw = zs[wid];
    int rcol = lane & 15;             // column this lane reduces
    int rrow = (lane >> 4) * 16;      // starting row of this lane's half
    for (int lb = 0; lb < LT_; lb += 32) {
        int l = lb + lane;
        float z0 = z0r[l], z1 = z1r[l];
        if (prev) {
            z0 = fmaf((z0 - m0r[l]) * r0r[l], lng, lnb);
            z1 = fmaf((z1 - m1r[l]) * r1r[l], lng, lnb);
        }
        zw[lane] = pk2(z0, z1);
        __syncwarp();
        u64 yhalf[2];
        #pragma unroll
        for (int sub = 0; sub < 2; sub++) {
            #pragma unroll
            for (int t = 0; t < 16; t++) {
                u64 ztp = zw[sub*16 + t];
                u64 nsr = fma2_(LMx2, sr, fma2_(nLMy2, si, ztp));
                u64 nsi = fma2_(LMy2, sr, mul2_(LMx2, si));
                sr = nsr; si = nsi;
                bw[lane][t] = fma2_(CMx2, sr, mul2_(nCMy2, si));
            }
            __syncwarp();
            u64 acc = 0ULL;
            #pragma unroll
            for (int r = 0; r < 16; r++) acc = add2_(acc, bw[rrow + r][rcol]);
            yhalf[sub] = acc;
            __syncwarp();
        }
        // combine halves: full column sum lands on both lane and lane^16
        u64 f0 = add2_(yhalf[0], __shfl_xor_sync(0xffffffffu, yhalf[0], 16));
        u64 f1 = add2_(yhalf[1], __shfl_xor_sync(0xffffffffu, yhalf[1], 16));
        u64 ysel = (lane < 16) ? f0 : f1;   // lane's own t = lane: sub = lane>>4, col = lane&15
        float y0, y1;
        upk2(ysel, y0, y1);
        float yv0 = fmaf(D, z0, y0);
        float yv1 = fmaf(D, z1, y1);
        float ge0 = 0.5f * yv0 * (1.0f + erff(yv0 * 0.70710678118654752f));
        float ge1 = 0.5f * yv1 * (1.0f + erff(yv1 * 0.70710678118654752f));
        __half h0 = __float2half_rn(ge0);
        __half h1 = __float2half_rn(ge1);
        xh0[l] = h0; xl0[l] = __float2half_rn(ge0 - __half2float(h0));
        xh1[l] = h1; xl1[l] = __float2half_rn(ge1 - __half2float(h1));
        __syncwarp();
    }
}

// ---------------- K3: mma.sync fp16-split GEMM + GLU + residual + LN stats -----
#define BK_ 32
#define AP_ 40
#define BP_ 136
#define NCH_ (DM_/BK_)   // 12

struct Buf {
    __half aa_hi[64][AP_], aa_lo[64][AP_];
    __half ag_hi[64][AP_], ag_lo[64][AP_];
    __half bhi[BK_][BP_],  blo[BK_][BP_];
};
struct Epi {
    float gbuf[64][132];
    float st_s[128][16];
    float st_q[128][16];
};
struct SmemG {
    union { Buf buf[2]; Epi ep; };
};

__device__ __forceinline__ void ldmx4(uint32_t* r, uint32_t addr) {
    asm volatile("ldmatrix.sync.aligned.m8n8.x4.shared.b16 {%0,%1,%2,%3}, [%4];"
        : "=r"(r[0]), "=r"(r[1]), "=r"(r[2]), "=r"(r[3]) : "r"(addr));
}
__device__ __forceinline__ void ldmx4t(uint32_t* r, uint32_t addr) {
    asm volatile("ldmatrix.sync.aligned.m8n8.x4.trans.shared.b16 {%0,%1,%2,%3}, [%4];"
        : "=r"(r[0]), "=r"(r[1]), "=r"(r[2]), "=r"(r[3]) : "r"(addr));
}
__device__ __forceinline__ void mma16816(float* c, const uint32_t* a, uint32_t b0, uint32_t b1) {
    asm volatile("mma.sync.aligned.m16n8k16.row.col.f32.f16.f16.f32 "
        "{%0,%1,%2,%3}, {%4,%5,%6,%7}, {%8,%9}, {%0,%1,%2,%3};"
        : "+f"(c[0]), "+f"(c[1]), "+f"(c[2]), "+f"(c[3])
        : "r"(a[0]), "r"(a[1]), "r"(a[2]), "r"(a[3]), "r"(b0), "r"(b1));
}

__device__ __forceinline__ void load_chunk(Buf* bf, const __half* whL, const __half* wlL,
                                           const __half* xhB, const __half* xlB,
                                           int o0, int k0, int tid) {
    int row = tid >> 2, q = (tid & 3) * 8;
    size_t offA = (size_t)(o0 + row)*DM_ + k0 + q;
    size_t offG = (size_t)(384 + o0 + row)*DM_ + k0 + q;
    cpa16(smem_u32(&bf->aa_hi[row][q]), whL + offA);
    cpa16(smem_u32(&bf->aa_lo[row][q]), wlL + offA);
    cpa16(smem_u32(&bf->ag_hi[row][q]), whL + offG);
    cpa16(smem_u32(&bf->ag_lo[row][q]), wlL + offG);
    int br = tid >> 3, bq = (tid & 7) * 8;
    const __half* xh = xhB + (size_t)(k0 + br)*LT_;
    const __half* xl = xlB + (size_t)(k0 + br)*LT_;
    cpa16(smem_u32(&bf->bhi[br][bq     ]), xh + bq);
    cpa16(smem_u32(&bf->bhi[br][bq + 64]), xh + bq + 64);
    cpa16(smem_u32(&bf->blo[br][bq     ]), xl + bq);
    cpa16(smem_u32(&bf->blo[br][bq + 64]), xl + bq + 64);
}

__global__ __launch_bounds__(256, 2) void k_gemm_mma(const float* __restrict__ conv_b,
                                                     const float* __restrict__ ln_g,
                                                     const float* __restrict__ ln_b,
                                                     int layer, int prev) {
    extern __shared__ char dsm[];
    SmemG* sm = (SmemG*)dsm;
    int tid = threadIdx.x;
    int l0 = blockIdx.x * 128;
    int o0 = blockIdx.y * 64;
    int b  = blockIdx.z;
    const __half* whL = g_wh + (size_t)layer*768*DM_;
    const __half* wlL = g_wl + (size_t)layer*768*DM_;
    const __half* xhB = g_xh + (size_t)b*DM_*LT_ + l0;
    const __half* xlB = g_xl + (size_t)b*DM_*LT_ + l0;
    const float*  cb  = conv_b + layer*768;

    int w = tid >> 5, lane = tid & 31;
    bool is_g = (w >= 4);
    int wl = w & 3;
    int m_off = (wl & 1) * 32;
    int n_off = (wl >> 1) * 64;

    float c[2][8][4];
    #pragma unroll
    for (int i = 0; i < 2; i++)
        #pragma unroll
        for (int j = 0; j < 8; j++)
            #pragma unroll
            for (int q = 0; q < 4; q++) c[i][j][q] = 0.0f;

    load_chunk(&sm->buf[0], whL, wlL, xhB, xlB, o0, 0, tid);
    asm volatile("cp.async.commit_group;" ::: "memory");

    for (int ch = 0; ch < NCH_; ch++) {
        if (ch + 1 < NCH_) {
            load_chunk(&sm->buf[(ch+1)&1], whL, wlL, xhB, xlB, o0, (ch+1)*BK_, tid);
            asm volatile("cp.async.commit_group;" ::: "memory");
            asm volatile("cp.async.wait_group 1;" ::: "memory");
        } else {
            asm volatile("cp.async.wait_group 0;" ::: "memory");
        }
        __syncthreads();
        Buf* bf = &sm->buf[ch & 1];
        const __half (*Ahi)[AP_] = is_g ? bf->ag_hi : bf->aa_hi;
        const __half (*Alo)[AP_] = is_g ? bf->ag_lo : bf->aa_lo;
        #pragma unroll
        for (int s = 0; s < 2; s++) {
            uint32_t ah[2][4], al[2][4];
            int arow = m_off + (lane & 15);
            int acol = s*16 + (lane >> 4)*8;
            #pragma unroll
            for (int mt = 0; mt < 2; mt++) {
                ldmx4 (ah[mt], smem_u32(&Ahi[arow + mt*16][acol]));
                ldmx4 (al[mt], smem_u32(&Alo[arow + mt*16][acol]));
            }
            int brow = s*16 + (lane & 15);
            #pragma unroll
            for (int g4 = 0; g4 < 4; g4++) {
                int bcol = n_off + g4*16 + (lane >> 4)*8;
                uint32_t bh[4], bl_[4];
                ldmx4t(bh,  smem_u32(&bf->bhi[brow][bcol]));
                ldmx4t(bl_, smem_u32(&bf->blo[brow][bcol]));
                #pragma unroll
                for (int hf = 0; hf < 2; hf++) {
                    int nt = g4*2 + hf;
                    uint32_t b0h = bh[hf*2],  b1h = bh[hf*2+1];
                    uint32_t b0l = bl_[hf*2], b1l = bl_[hf*2+1];
                    #pragma unroll
                    for (int mt = 0; mt < 2; mt++) {
                        mma16816(c[mt][nt], ah[mt], b0h, b1h);
                        mma16816(c[mt][nt], ah[mt], b0l, b1l);
                        mma16816(c[mt][nt], al[mt], b0h, b1h);
                    }
                }
            }
        }
        __syncthreads();
    }

    // ---- epilogue: g stash -> GLU + residual(+LN of prev) -> LN stats ----------
    if (is_g) {
        #pragma unroll
        for (int mt = 0; mt < 2; mt++)
            #pragma unroll
            for (int nt = 0; nt < 8; nt++) {
                int r  = m_off + mt*16 + (lane >> 2);
                int cc = n_off + nt*8 + (lane & 3)*2;
                *(float2*)&sm->ep.gbuf[r  ][cc] = make_float2(c[mt][nt][0], c[mt][nt][1]);
                *(float2*)&sm->ep.gbuf[r+8][cc] = make_float2(c[mt][nt][2], c[mt][nt][3]);
            }
    }
    __syncthreads();
    if (!is_g) {
        size_t bL = (size_t)b*LT_ + l0;
        const float* lngL = ln_g + (prev ? (layer-1)*DM_ : 0);
        const float* lnbL = ln_b + (prev ? (layer-1)*DM_ : 0);
        float ba[2][2], bg[2][2], lgv[2][2], lbv[2][2];
        #pragma unroll
        for (int mt = 0; mt < 2; mt++)
            #pragma unroll
            for (int rh = 0; rh < 2; rh++) {
                int o = o0 + m_off + mt*16 + (lane >> 2) + rh*8;
                ba[mt][rh] = cb[o]; bg[mt][rh] = cb[384 + o];
                lgv[mt][rh] = prev ? lngL[o] : 1.0f;
                lbv[mt][rh] = prev ? lnbL[o] : 0.0f;
            }
        int slot = (wl & 1)*8 + (lane >> 2);
        #pragma unroll
        for (int nt = 0; nt < 8; nt++) {
            int cc = n_off + nt*8 + (lane & 3)*2;
            float2 mv = make_float2(0.f, 0.f), rv = make_float2(1.f, 1.f);
            if (prev) {
                mv = *(const float2*)&g_m[bL + cc];
                rv = *(const float2*)&g_r[bL + cc];
            }
            float s0 = 0.f, s1 = 0.f, q0 = 0.f, q1 = 0.f;
            #pragma unroll
            for (int mt = 0; mt < 2; mt++)
                #pragma unroll
                for (int rh = 0; rh < 2; rh++) {
                    int row = m_off + mt*16 + (lane >> 2) + rh*8;
                    int o   = o0 + row;
                    float2 gv = *(float2*)&sm->ep.gbuf[row][cc];
                    size_t gix = ((size_t)(b*DM_ + o))*LT_ + l0 + cc;
                    float2 res;
                    if (prev) {
                        float2 raw = *(const float2*)&g_zt[gix];
                        res.x = fmaf((raw.x - mv.x) * rv.x, lgv[mt][rh], lbv[mt][rh]);
                        res.y = fmaf((raw.y - mv.y) * rv.y, lgv[mt][rh], lbv[mt][rh]);
                    } else {
                        res = *(const float2*)&g_z[gix];
                    }
                    float a0 = c[mt][nt][rh*2+0] + ba[mt][rh];
                    float a1 = c[mt][nt][rh*2+1] + ba[mt][rh];
                    float g0 = gv.x + bg[mt][rh], g1 = gv.y + bg[mt][rh];
                    float sg0 = 1.0f / (1.0f + expf(-g0));
                    float sg1 = 1.0f / (1.0f + expf(-g1));
                    float v0 = fmaf(a0, sg0, res.x);
                    float v1 = fmaf(a1, sg1, res.y);
                    *(float2*)&g_zt[gix] = make_float2(v0, v1);
                    s0 += v0; q0 = fmaf(v0, v0, q0);
                    s1 += v1; q1 = fmaf(v1, v1, q1);
                }
            sm->ep.st_s[cc  ][slot] = s0;
            sm->ep.st_s[cc+1][slot] = s1;
            sm->ep.st_q[cc  ][slot] = q0;
            sm->ep.st_q[cc+1][slot] = q1;
        }
    }
    __syncthreads();
    {
        int col = tid >> 1, which = tid & 1;
        const float* arr = which ? &sm->ep.st_q[col][0] : &sm->ep.st_s[col][0];
        float s = 0.f;
        #pragma unroll
        for (int k = 0; k < 16; k++) s += arr[k];
        float* dst = which ? g_sq : g_sum;
        atomicAdd(dst + (size_t)b*LT_ + l0 + col, s);
    }
}

// ---------------- K3b: finalize LN stats + re-zero accumulators -----------------
__global__ void k_statfin() {
    int i = blockIdx.x * blockDim.x + threadIdx.x;   // B_*LT_ threads
    float s = g_sum[i], q = g_sq[i];
    float m = s * (1.0f/DM_);
    float v = q * (1.0f/DM_) - m*m;
    g_m[i] = m;
    g_r[i] = rsqrtf(v + EPS_);
    g_sum[i] = 0.0f;
    g_sq[i]  = 0.0f;
}

// ---------------- K5: output projections (normalize final z on the fly) --------
__global__ __launch_bounds__(256) void k_final(const float* __restrict__ W_pa,
                                               const float* __restrict__ b_pa,
                                               const float* __restrict__ W_ps,
                                               const float* __restrict__ b_ps,
                                               const float* __restrict__ ln_g,
                                               const float* __restrict__ ln_b,
                                               float* __restrict__ out) {
    __shared__ float zt[DM_][32];
    int b  = blockIdx.y;
    int l0 = blockIdx.x * 8;
    int p  = threadIdx.x & 31;
    int hg = threadIdx.x >> 5;
    size_t base = (size_t)b*LT_ + l0*4;
    float m = g_m[base + p];
    float r = g_r[base + p];
    const float* lg = ln_g + (NL_-1)*DM_;
    const float* lb = ln_b + (NL_-1)*DM_;
    for (int h = hg; h < DM_; h += 8) {
        float v = g_zt[((size_t)(b*DM_ + h))*LT_ + l0*4 + p];
        zt[h][p] = fmaf((v - m) * r, lg[h], lb[h]);
    }
    __syncthreads();
    int t = threadIdx.x;
    if (t < 8*(SD_ + AD_)) {
        int li = t / (SD_ + AD_);
        int o  = t % (SD_ + AD_);
        int l  = l0 + li;
        if (o < SD_) {
            int pp = li*4 + 3;
            float acc = b_ps[o];
            #pragma unroll 8
            for (int h = 0; h < DM_; h++) acc = fmaf(zt[h][pp], W_ps[h*SD_ + o], acc);
            out[((size_t)(b*L_ + l))*SD_ + o] = acc;
        } else {
            int o2 = o - SD_;
            int pp = li*4 + 2;
            float acc = b_pa[o2];
            #pragma unroll 8
            for (int h = 0; h < DM_; h++) acc = fmaf(zt[h][pp], W_pa[h*AD_ + o2], acc);
            out[(size_t)B_*L_*SD_ + ((size_t)(b*L_ + l))*AD_ + o2] = acc;
        }
    }
}

// ---------------- launch --------------------------------------------------------
extern "C" void kernel_launch(void* const* d_in, const int* in_sizes, int n_in,
                              void* d_out, int out_size) {
    const float* states     = (const float*)d_in[0];
    const float* actions    = (const float*)d_in[1];
    const float* rtg        = (const float*)d_in[2];
    const float* ctg        = (const float*)d_in[3];
    const int*   tsteps     = (const int*  )d_in[4];
    const float* W_es       = (const float*)d_in[5];
    const float* b_es       = (const float*)d_in[6];
    const float* W_ea       = (const float*)d_in[7];
    const float* b_ea       = (const float*)d_in[8];
    const float* W_er       = (const float*)d_in[9];
    const float* b_er       = (const float*)d_in[10];
    const float* W_ec       = (const float*)d_in[11];
    const float* b_ec       = (const float*)d_in[12];
    const float* E_t        = (const float*)d_in[13];
    const float* log_dt     = (const float*)d_in[14];
    const float* C_ri       = (const float*)d_in[15];
    const float* log_A_real = (const float*)d_in[16];
    const float* A_imag     = (const float*)d_in[17];
    const float* D_skip     = (const float*)d_in[18];
    const float* conv_w     = (const float*)d_in[19];
    const float* conv_b     = (const float*)d_in[20];
    const float* ln_g       = (const float*)d_in[21];
    const float* ln_b       = (const float*)d_in[22];
    const float* W_pa       = (const float*)d_in[23];
    const float* b_pa       = (const float*)d_in[24];
    const float* W_ps       = (const float*)d_in[25];
    const float* b_ps       = (const float*)d_in[26];

    cudaFuncSetAttribute(k_gemm_mma, cudaFuncAttributeMaxDynamicSharedMemorySize,
                         (int)sizeof(SmemG));

    k_precompute<<<(NL_*DM_*N2_ + 255)/256, 256>>>(log_dt, C_ri, log_A_real, A_imag);
    k_prep_w<<<(NL_*768*DM_ + 255)/256, 256>>>(conv_w);
    k_embed<<<B_*L_, DM_>>>(states, actions, rtg, ctg, tsteps,
                            W_es, b_es, W_ea, b_ea, W_er, b_er, W_ec, b_ec, E_t);
    for (int i = 0; i < NL_; i++) {
        int prev = (i > 0) ? 1 : 0;
        k_s4d<<<(DM_*(B_/2))/4, 128>>>(D_skip, ln_g, ln_b, i, prev);
        dim3 g3(LT_/128, DM_/64, B_);
        k_gemm_mma<<<g3, 256, sizeof(SmemG)>>>(conv_b, ln_g, ln_b, i, prev);
        k_statfin<<<(B_*LT_)/256, 256>>>();
    }
    dim3 g5(L_/8, B_);
    k_final<<<g5, 256>>>(W_pa, b_pa, W_ps, b_ps, ln_g, ln_b, (float*)d_out);
}

// round 8
// speedup vs baseline: 1.0237x; 1.0237x over previous
#include <cuda_runtime.h>
#include <cuda_fp16.h>
#include <math.h>
#include <stdint.h>

#define B_  32
#define L_  512
#define SD_ 17
#define AD_ 6
#define DM_ 384
#define NL_ 12
#define N2_ 32
#define LT_ 2048           // 4*L
#define EPS_ 1e-5f

typedef unsigned long long u64;

// ---------------- scratch (device globals; no allocations allowed) -------------
__device__ float  g_z  [B_*DM_*LT_];    // embed output (layer-0 input)
__device__ float  g_zt [B_*DM_*LT_];    // raw residual stream (pre-LN), in-place
__device__ __half g_xh [B_*DM_*LT_];    // gelu output, fp16 hi
__device__ __half g_xl [B_*DM_*LT_];    // gelu output, fp16 lo
__device__ __half g_wh [NL_*768*DM_];   // conv_w fp16 hi
__device__ __half g_wl [NL_*768*DM_];   // conv_w fp16 lo
__device__ float2 g_lam[NL_*DM_*N2_];
__device__ float2 g_cm [NL_*DM_*N2_];
__device__ float  g_sum[B_*LT_];        // LN partial sums (zeroed by k_statfin)
__device__ float  g_sq [B_*LT_];
__device__ float  g_m  [B_*LT_];        // LN mean
__device__ float  g_r  [B_*LT_];        // LN rstd

__device__ __forceinline__ uint32_t smem_u32(const void* p) {
    uint32_t a;
    asm("{ .reg .u64 t; cvta.to.shared.u64 t, %1; cvt.u32.u64 %0, t; }" : "=r"(a) : "l"(p));
    return a;
}
__device__ __forceinline__ void cpa16(uint32_t dst, const void* src) {
    asm volatile("cp.async.cg.shared.global [%0], [%1], 16;" :: "r"(dst), "l"(src) : "memory");
}
// ---- packed f32x2 helpers ----
__device__ __forceinline__ u64 pk2(float x, float y) {
    u64 r; asm("mov.b64 %0, {%1,%2};" : "=l"(r) : "f"(x), "f"(y)); return r;
}
__device__ __forceinline__ void upk2(u64 v, float& x, float& y) {
    asm("mov.b64 {%0,%1}, %2;" : "=f"(x), "=f"(y) : "l"(v));
}
__device__ __forceinline__ u64 fma2_(u64 a, u64 b, u64 c) {
    u64 d; asm("fma.rn.f32x2 %0, %1, %2, %3;" : "=l"(d) : "l"(a), "l"(b), "l"(c)); return d;
}
__device__ __forceinline__ u64 mul2_(u64 a, u64 b) {
    u64 d; asm("mul.rn.f32x2 %0, %1, %2;" : "=l"(d) : "l"(a), "l"(b)); return d;
}
__device__ __forceinline__ u64 add2_(u64 a, u64 b) {
    u64 d; asm("add.rn.f32x2 %0, %1, %2;" : "=l"(d) : "l"(a), "l"(b)); return d;
}

// ---------------- K0: per-layer S4D coefficient precompute ---------------------
__global__ void k_precompute(const float* __restrict__ log_dt,
                             const float* __restrict__ C_ri,
                             const float* __restrict__ log_A_real,
                             const float* __restrict__ A_imag) {
    int idx = blockIdx.x * blockDim.x + threadIdx.x;
    if (idx >= NL_*DM_*N2_) return;
    int h = (idx / N2_) % DM_;
    int i = idx / (N2_*DM_);
    float dt = expf(log_dt[i*DM_ + h]);
    float Ar = -expf(log_A_real[idx]);
    float Ai = A_imag[idx];
    float dr = Ar*dt, di = Ai*dt;
    float er = expf(dr);
    float lr = er*cosf(di), li = er*sinf(di);
    float exr = lr - 1.0f, exi = li;
    float den = Ar*Ar + Ai*Ai;
    float wr = (exr*Ar + exi*Ai)/den;
    float wi = (exi*Ar - exr*Ai)/den;
    float Cr = C_ri[idx*2+0], Ci = C_ri[idx*2+1];
    g_lam[idx] = make_float2(lr, li);
    g_cm[idx]  = make_float2(2.0f*(Cr*wr - Ci*wi), 2.0f*(Cr*wi + Ci*wr));
}

// ---------------- K0b: weight split fp32 -> fp16 hi/lo -------------------------
__global__ void k_prep_w(const float* __restrict__ conv_w) {
    int idx = blockIdx.x * blockDim.x + threadIdx.x;
    if (idx >= NL_*768*DM_) return;
    float v = conv_w[idx];
    __half h = __float2half_rn(v);
    g_wh[idx] = h;
    g_wl[idx] = __float2half_rn(v - __half2float(h));
}

// ---------------- K1: embedding + interleave into (B, DM, 4L) ------------------
__global__ void k_embed(const float* __restrict__ states,
                        const float* __restrict__ actions,
                        const float* __restrict__ rtg,
                        const float* __restrict__ ctg,
                        const int*   __restrict__ tsteps,
                        const float* __restrict__ W_es, const float* __restrict__ b_es,
                        const float* __restrict__ W_ea, const float* __restrict__ b_ea,
                        const float* __restrict__ W_er, const float* __restrict__ b_er,
                        const float* __restrict__ W_ec, const float* __restrict__ b_ec,
                        const float* __restrict__ E_t) {
    int bl = blockIdx.x;
    int b = bl / L_, l = bl % L_;
    int h = threadIdx.x;
    int t = tsteps[bl];
    float te = E_t[t*DM_ + h];
    float r = rtg[bl], c = ctg[bl];
    float er = fmaf(r, W_er[h], b_er[h]) + te;
    float ec = fmaf(c, W_ec[h], b_ec[h]) + te;
    float es = b_es[h] + te;
    #pragma unroll
    for (int s = 0; s < SD_; s++) es = fmaf(states[bl*SD_ + s], W_es[s*DM_ + h], es);
    float ea = b_ea[h] + te;
    #pragma unroll
    for (int s = 0; s < AD_; s++) ea = fmaf(actions[bl*AD_ + s], W_ea[s*DM_ + h], ea);
    float* zr = g_z + ((size_t)(b*DM_ + h))*LT_ + 4*l;
    zr[0] = er; zr[1] = ec; zr[2] = es; zr[3] = ea;
}

// ---------------- K2: S4D recurrence, 2 batch-streams/lane via f32x2 -----------
// z chunk staged to smem once (LDS.64 broadcast in inner loop); cross-state
// reduce uses a 4-way accumulator tree to break the serial add chain.
__global__ __launch_bounds__(128) void k_s4d(const float* __restrict__ Dskip,
                                             const float* __restrict__ ln_g,
                                             const float* __restrict__ ln_b,
                                             int layer, int prev) {
    __shared__ u64 buf[4][32][33];
    __shared__ u64 zs [4][32];
    int wid  = threadIdx.x >> 5;
    int lane = threadIdx.x & 31;
    int gw = blockIdx.x*4 + wid;
    int h  = gw % DM_;
    int bq = gw / DM_;
    int b0 = bq*2, b1 = bq*2 + 1;
    int pidx = (layer*DM_ + h)*N2_ + lane;
    float2 LM = g_lam[pidx];
    float2 CM = g_cm[pidx];
    u64 LMx2  = pk2( LM.x,  LM.x);
    u64 LMy2  = pk2( LM.y,  LM.y);
    u64 nLMy2 = pk2(-LM.y, -LM.y);
    u64 CMx2  = pk2( CM.x,  CM.x);
    u64 nCMy2 = pk2(-CM.y, -CM.y);
    float D   = Dskip[layer*DM_ + h];
    float lng = 1.0f, lnb = 0.0f;
    const float* zsrc = prev ? g_zt : g_z;
    if (prev) { lng = ln_g[(layer-1)*DM_ + h]; lnb = ln_b[(layer-1)*DM_ + h]; }
    const float* z0r = zsrc + ((size_t)(b0*DM_ + h))*LT_;
    const float* z1r = zsrc + ((size_t)(b1*DM_ + h))*LT_;
    const float* m0r = g_m + (size_t)b0*LT_;
    const float* m1r = g_m + (size_t)b1*LT_;
    const float* r0r = g_r + (size_t)b0*LT_;
    const float* r1r = g_r + (size_t)b1*LT_;
    __half* xh0 = g_xh + ((size_t)(b0*DM_ + h))*LT_;
    __half* xl0 = g_xl + ((size_t)(b0*DM_ + h))*LT_;
    __half* xh1 = g_xh + ((size_t)(b1*DM_ + h))*LT_;
    __half* xl1 = g_xl + ((size_t)(b1*DM_ + h))*LT_;

    u64 sr = 0ULL, si = 0ULL;
    u64 (*bw)[33] = buf[wid];
    u64* zw = zs[wid];
    for (int lb = 0; lb < LT_; lb += 32) {
        int l = lb + lane;
        float z0 = z0r[l], z1 = z1r[l];
        if (prev) {
            z0 = fmaf((z0 - m0r[l]) * r0r[l], lng, lnb);
            z1 = fmaf((z1 - m1r[l]) * r1r[l], lng, lnb);
        }
        zw[lane] = pk2(z0, z1);
        __syncwarp();
        #pragma unroll
        for (int t = 0; t < 32; t++) {
            u64 ztp = zw[t];                               // LDS.64 broadcast
            u64 nsr = fma2_(LMx2, sr, fma2_(nLMy2, si, ztp));
            u64 nsi = fma2_(LMy2, sr, mul2_(LMx2, si));
            sr = nsr; si = nsi;
            bw[lane][t] = fma2_(CMx2, sr, mul2_(nCMy2, si));
        }
        __syncwarp();
        // 4-way tree reduce over states (reassociated: breaks serial add chain)
        u64 a0 = 0ULL, a1 = 0ULL, a2 = 0ULL, a3 = 0ULL;
        #pragma unroll
        for (int n = 0; n < 32; n += 4) {
            a0 = add2_(a0, bw[n  ][lane]);
            a1 = add2_(a1, bw[n+1][lane]);
            a2 = add2_(a2, bw[n+2][lane]);
            a3 = add2_(a3, bw[n+3][lane]);
        }
        u64 acc = add2_(add2_(a0, a1), add2_(a2, a3));
        float y0, y1;
        upk2(acc, y0, y1);
        float yv0 = fmaf(D, z0, y0);
        float yv1 = fmaf(D, z1, y1);
        float ge0 = 0.5f * yv0 * (1.0f + erff(yv0 * 0.70710678118654752f));
        float ge1 = 0.5f * yv1 * (1.0f + erff(yv1 * 0.70710678118654752f));
        __half h0 = __float2half_rn(ge0);
        __half h1 = __float2half_rn(ge1);
        xh0[l] = h0; xl0[l] = __float2half_rn(ge0 - __half2float(h0));
        xh1[l] = h1; xl1[l] = __float2half_rn(ge1 - __half2float(h1));
        __syncwarp();
    }
}

// ---------------- K3: mma.sync fp16-split GEMM + GLU + residual + LN stats -----
#define BK_ 32
#define AP_ 40
#define BP_ 136
#define NCH_ (DM_/BK_)   // 12

struct Buf {
    __half aa_hi[64][AP_], aa_lo[64][AP_];
    __half ag_hi[64][AP_], ag_lo[64][AP_];
    __half bhi[BK_][BP_],  blo[BK_][BP_];
};
struct Epi {
    float gbuf[64][132];
    float st_s[128][16];
    float st_q[128][16];
};
struct SmemG {
    union { Buf buf[2]; Epi ep; };
};

__device__ __forceinline__ void ldmx4(uint32_t* r, uint32_t addr) {
    asm volatile("ldmatrix.sync.aligned.m8n8.x4.shared.b16 {%0,%1,%2,%3}, [%4];"
        : "=r"(r[0]), "=r"(r[1]), "=r"(r[2]), "=r"(r[3]) : "r"(addr));
}
__device__ __forceinline__ void ldmx4t(uint32_t* r, uint32_t addr) {
    asm volatile("ldmatrix.sync.aligned.m8n8.x4.trans.shared.b16 {%0,%1,%2,%3}, [%4];"
        : "=r"(r[0]), "=r"(r[1]), "=r"(r[2]), "=r"(r[3]) : "r"(addr));
}
__device__ __forceinline__ void mma16816(float* c, const uint32_t* a, uint32_t b0, uint32_t b1) {
    asm volatile("mma.sync.aligned.m16n8k16.row.col.f32.f16.f16.f32 "
        "{%0,%1,%2,%3}, {%4,%5,%6,%7}, {%8,%9}, {%0,%1,%2,%3};"
        : "+f"(c[0]), "+f"(c[1]), "+f"(c[2]), "+f"(c[3])
        : "r"(a[0]), "r"(a[1]), "r"(a[2]), "r"(a[3]), "r"(b0), "r"(b1));
}

__device__ __forceinline__ void load_chunk(Buf* bf, const __half* whL, const __half* wlL,
                                           const __half* xhB, const __half* xlB,
                                           int o0, int k0, int tid) {
    int row = tid >> 2, q = (tid & 3) * 8;
    size_t offA = (size_t)(o0 + row)*DM_ + k0 + q;
    size_t offG = (size_t)(384 + o0 + row)*DM_ + k0 + q;
    cpa16(smem_u32(&bf->aa_hi[row][q]), whL + offA);
    cpa16(smem_u32(&bf->aa_lo[row][q]), wlL + offA);
    cpa16(smem_u32(&bf->ag_hi[row][q]), whL + offG);
    cpa16(smem_u32(&bf->ag_lo[row][q]), wlL + offG);
    int br = tid >> 3, bq = (tid & 7) * 8;
    const __half* xh = xhB + (size_t)(k0 + br)*LT_;
    const __half* xl = xlB + (size_t)(k0 + br)*LT_;
    cpa16(smem_u32(&bf->bhi[br][bq     ]), xh + bq);
    cpa16(smem_u32(&bf->bhi[br][bq + 64]), xh + bq + 64);
    cpa16(smem_u32(&bf->blo[br][bq     ]), xl + bq);
    cpa16(smem_u32(&bf->blo[br][bq + 64]), xl + bq + 64);
}

__global__ __launch_bounds__(256, 2) void k_gemm_mma(const float* __restrict__ conv_b,
                                                     const float* __restrict__ ln_g,
                                                     const float* __restrict__ ln_b,
                                                     int layer, int prev) {
    extern __shared__ char dsm[];
    SmemG* sm = (SmemG*)dsm;
    int tid = threadIdx.x;
    int l0 = blockIdx.x * 128;
    int o0 = blockIdx.y * 64;
    int b  = blockIdx.z;
    const __half* whL = g_wh + (size_t)layer*768*DM_;
    const __half* wlL = g_wl + (size_t)layer*768*DM_;
    const __half* xhB = g_xh + (size_t)b*DM_*LT_ + l0;
    const __half* xlB = g_xl + (size_t)b*DM_*LT_ + l0;
    const float*  cb  = conv_b + layer*768;

    int w = tid >> 5, lane = tid & 31;
    bool is_g = (w >= 4);
    int wl = w & 3;
    int m_off = (wl & 1) * 32;
    int n_off = (wl >> 1) * 64;

    float c[2][8][4];
    #pragma unroll
    for (int i = 0; i < 2; i++)
        #pragma unroll
        for (int j = 0; j < 8; j++)
            #pragma unroll
            for (int q = 0; q < 4; q++) c[i][j][q] = 0.0f;

    load_chunk(&sm->buf[0], whL, wlL, xhB, xlB, o0, 0, tid);
    asm volatile("cp.async.commit_group;" ::: "memory");

    for (int ch = 0; ch < NCH_; ch++) {
        if (ch + 1 < NCH_) {
            load_chunk(&sm->buf[(ch+1)&1], whL, wlL, xhB, xlB, o0, (ch+1)*BK_, tid);
            asm volatile("cp.async.commit_group;" ::: "memory");
            asm volatile("cp.async.wait_group 1;" ::: "memory");
        } else {
            asm volatile("cp.async.wait_group 0;" ::: "memory");
        }
        __syncthreads();
        Buf* bf = &sm->buf[ch & 1];
        const __half (*Ahi)[AP_] = is_g ? bf->ag_hi : bf->aa_hi;
        const __half (*Alo)[AP_] = is_g ? bf->ag_lo : bf->aa_lo;
        #pragma unroll
        for (int s = 0; s < 2; s++) {
            uint32_t ah[2][4], al[2][4];
            int arow = m_off + (lane & 15);
            int acol = s*16 + (lane >> 4)*8;
            #pragma unroll
            for (int mt = 0; mt < 2; mt++) {
                ldmx4 (ah[mt], smem_u32(&Ahi[arow + mt*16][acol]));
                ldmx4 (al[mt], smem_u32(&Alo[arow + mt*16][acol]));
            }
            int brow = s*16 + (lane & 15);
            #pragma unroll
            for (int g4 = 0; g4 < 4; g4++) {
                int bcol = n_off + g4*16 + (lane >> 4)*8;
                uint32_t bh[4], bl_[4];
                ldmx4t(bh,  smem_u32(&bf->bhi[brow][bcol]));
                ldmx4t(bl_, smem_u32(&bf->blo[brow][bcol]));
                #pragma unroll
                for (int hf = 0; hf < 2; hf++) {
                    int nt = g4*2 + hf;
                    uint32_t b0h = bh[hf*2],  b1h = bh[hf*2+1];
                    uint32_t b0l = bl_[hf*2], b1l = bl_[hf*2+1];
                    #pragma unroll
                    for (int mt = 0; mt < 2; mt++) {
                        mma16816(c[mt][nt], ah[mt], b0h, b1h);
                        mma16816(c[mt][nt], ah[mt], b0l, b1l);
                        mma16816(c[mt][nt], al[mt], b0h, b1h);
                    }
                }
            }
        }
        __syncthreads();
    }

    // ---- epilogue: g stash -> GLU + residual(+LN of prev) -> LN stats ----------
    if (is_g) {
        #pragma unroll
        for (int mt = 0; mt < 2; mt++)
            #pragma unroll
            for (int nt = 0; nt < 8; nt++) {
                int r  = m_off + mt*16 + (lane >> 2);
                int cc = n_off + nt*8 + (lane & 3)*2;
                *(float2*)&sm->ep.gbuf[r  ][cc] = make_float2(c[mt][nt][0], c[mt][nt][1]);
                *(float2*)&sm->ep.gbuf[r+8][cc] = make_float2(c[mt][nt][2], c[mt][nt][3]);
            }
    }
    __syncthreads();
    if (!is_g) {
        size_t bL = (size_t)b*LT_ + l0;
        const float* lngL = ln_g + (prev ? (layer-1)*DM_ : 0);
        const float* lnbL = ln_b + (prev ? (layer-1)*DM_ : 0);
        float ba[2][2], bg[2][2], lgv[2][2], lbv[2][2];
        #pragma unroll
        for (int mt = 0; mt < 2; mt++)
            #pragma unroll
            for (int rh = 0; rh < 2; rh++) {
                int o = o0 + m_off + mt*16 + (lane >> 2) + rh*8;
                ba[mt][rh] = cb[o]; bg[mt][rh] = cb[384 + o];
                lgv[mt][rh] = prev ? lngL[o] : 1.0f;
                lbv[mt][rh] = prev ? lnbL[o] : 0.0f;
            }
        int slot = (wl & 1)*8 + (lane >> 2);
        #pragma unroll
        for (int nt = 0; nt < 8; nt++) {
            int cc = n_off + nt*8 + (lane & 3)*2;
            float2 mv = make_float2(0.f, 0.f), rv = make_float2(1.f, 1.f);
            if (prev) {
                mv = *(const float2*)&g_m[bL + cc];
                rv = *(const float2*)&g_r[bL + cc];
            }
            float s0 = 0.f, s1 = 0.f, q0 = 0.f, q1 = 0.f;
            #pragma unroll
            for (int mt = 0; mt < 2; mt++)
                #pragma unroll
                for (int rh = 0; rh < 2; rh++) {
                    int row = m_off + mt*16 + (lane >> 2) + rh*8;
                    int o   = o0 + row;
                    float2 gv = *(float2*)&sm->ep.gbuf[row][cc];
                    size_t gix = ((size_t)(b*DM_ + o))*LT_ + l0 + cc;
                    float2 res;
                    if (prev) {
                        float2 raw = *(const float2*)&g_zt[gix];
                        res.x = fmaf((raw.x - mv.x) * rv.x, lgv[mt][rh], lbv[mt][rh]);
                        res.y = fmaf((raw.y - mv.y) * rv.y, lgv[mt][rh], lbv[mt][rh]);
                    } else {
                        res = *(const float2*)&g_z[gix];
                    }
                    float a0 = c[mt][nt][rh*2+0] + ba[mt][rh];
                    float a1 = c[mt][nt][rh*2+1] + ba[mt][rh];
                    float g0 = gv.x + bg[mt][rh], g1 = gv.y + bg[mt][rh];
                    float sg0 = 1.0f / (1.0f + expf(-g0));
                    float sg1 = 1.0f / (1.0f + expf(-g1));
                    float v0 = fmaf(a0, sg0, res.x);
                    float v1 = fmaf(a1, sg1, res.y);
                    *(float2*)&g_zt[gix] = make_float2(v0, v1);
                    s0 += v0; q0 = fmaf(v0, v0, q0);
                    s1 += v1; q1 = fmaf(v1, v1, q1);
                }
            sm->ep.st_s[cc  ][slot] = s0;
            sm->ep.st_s[cc+1][slot] = s1;
            sm->ep.st_q[cc  ][slot] = q0;
            sm->ep.st_q[cc+1][slot] = q1;
        }
    }
    __syncthreads();
    {
        int col = tid >> 1, which = tid & 1;
        const float* arr = which ? &sm->ep.st_q[col][0] : &sm->ep.st_s[col][0];
        float s = 0.f;
        #pragma unroll
        for (int k = 0; k < 16; k++) s += arr[k];
        float* dst = which ? g_sq : g_sum;
        atomicAdd(dst + (size_t)b*LT_ + l0 + col, s);
    }
}

// ---------------- K3b: finalize LN stats + re-zero accumulators -----------------
__global__ void k_statfin() {
    int i = blockIdx.x * blockDim.x + threadIdx.x;   // B_*LT_ threads
    float s = g_sum[i], q = g_sq[i];
    float m = s * (1.0f/DM_);
    float v = q * (1.0f/DM_) - m*m;
    g_m[i] = m;
    g_r[i] = rsqrtf(v + EPS_);
    g_sum[i] = 0.0f;
    g_sq[i]  = 0.0f;
}

// ---------------- K5: output projections (normalize final z on the fly) --------
__global__ __launch_bounds__(256) void k_final(const float* __restrict__ W_pa,
                                               const float* __restrict__ b_pa,
                                               const float* __restrict__ W_ps,
                                               const float* __restrict__ b_ps,
                                               const float* __restrict__ ln_g,
                                               const float* __restrict__ ln_b,
                                               float* __restrict__ out) {
    __shared__ float zt[DM_][32];
    int b  = blockIdx.y;
    int l0 = blockIdx.x * 8;
    int p  = threadIdx.x & 31;
    int hg = threadIdx.x >> 5;
    size_t base = (size_t)b*LT_ + l0*4;
    float m = g_m[base + p];
    float r = g_r[base + p];
    const float* lg = ln_g + (NL_-1)*DM_;
    const float* lb = ln_b + (NL_-1)*DM_;
    for (int h = hg; h < DM_; h += 8) {
        float v = g_zt[((size_t)(b*DM_ + h))*LT_ + l0*4 + p];
        zt[h][p] = fmaf((v - m) * r, lg[h], lb[h]);
    }
    __syncthreads();
    int t = threadIdx.x;
    if (t < 8*(SD_ + AD_)) {
        int li = t / (SD_ + AD_);
        int o  = t % (SD_ + AD_);
        int l  = l0 + li;
        if (o < SD_) {
            int pp = li*4 + 3;
            float acc = b_ps[o];
            #pragma unroll 8
            for (int h = 0; h < DM_; h++) acc = fmaf(zt[h][pp], W_ps[h*SD_ + o], acc);
            out[((size_t)(b*L_ + l))*SD_ + o] = acc;
        } else {
            int o2 = o - SD_;
            int pp = li*4 + 2;
            float acc = b_pa[o2];
            #pragma unroll 8
            for (int h = 0; h < DM_; h++) acc = fmaf(zt[h][pp], W_pa[h*AD_ + o2], acc);
            out[(size_t)B_*L_*SD_ + ((size_t)(b*L_ + l))*AD_ + o2] = acc;
        }
    }
}

// ---------------- launch --------------------------------------------------------
extern "C" void kernel_launch(void* const* d_in, const int* in_sizes, int n_in,
                              void* d_out, int out_size) {
    const float* states     = (const float*)d_in[0];
    const float* actions    = (const float*)d_in[1];
    const float* rtg        = (const float*)d_in[2];
    const float* ctg        = (const float*)d_in[3];
    const int*   tsteps     = (const int*  )d_in[4];
    const float* W_es       = (const float*)d_in[5];
    const float* b_es       = (const float*)d_in[6];
    const float* W_ea       = (const float*)d_in[7];
    const float* b_ea       = (const float*)d_in[8];
    const float* W_er       = (const float*)d_in[9];
    const float* b_er       = (const float*)d_in[10];
    const float* W_ec       = (const float*)d_in[11];
    const float* b_ec       = (const float*)d_in[12];
    const float* E_t        = (const float*)d_in[13];
    const float* log_dt     = (const float*)d_in[14];
    const float* C_ri       = (const float*)d_in[15];
    const float* log_A_real = (const float*)d_in[16];
    const float* A_imag     = (const float*)d_in[17];
    const float* D_skip     = (const float*)d_in[18];
    const float* conv_w     = (const float*)d_in[19];
    const float* conv_b     = (const float*)d_in[20];
    const float* ln_g       = (const float*)d_in[21];
    const float* ln_b       = (const float*)d_in[22];
    const float* W_pa       = (const float*)d_in[23];
    const float* b_pa       = (const float*)d_in[24];
    const float* W_ps       = (const float*)d_in[25];
    const float* b_ps       = (const float*)d_in[26];

    cudaFuncSetAttribute(k_gemm_mma, cudaFuncAttributeMaxDynamicSharedMemorySize,
                         (int)sizeof(SmemG));

    k_precompute<<<(NL_*DM_*N2_ + 255)/256, 256>>>(log_dt, C_ri, log_A_real, A_imag);
    k_prep_w<<<(NL_*768*DM_ + 255)/256, 256>>>(conv_w);
    k_embed<<<B_*L_, DM_>>>(states, actions, rtg, ctg, tsteps,
                            W_es, b_es, W_ea, b_ea, W_er, b_er, W_ec, b_ec, E_t);
    for (int i = 0; i < NL_; i++) {
        int prev = (i > 0) ? 1 : 0;
        k_s4d<<<(DM_*(B_/2))/4, 128>>>(D_skip, ln_g, ln_b, i, prev);
        dim3 g3(LT_/128, DM_/64, B_);
        k_gemm_mma<<<g3, 256, sizeof(SmemG)>>>(conv_b, ln_g, ln_b, i, prev);
        k_statfin<<<(B_*LT_)/256, 256>>>();
    }
    dim3 g5(L_/8, B_);
    k_final<<<g5, 256>>>(W_pa, b_pa, W_ps, b_ps, ln_g, ln_b, (float*)d_out);
}

// round 9
// speedup vs baseline: 1.0262x; 1.0025x over previous
#include <cuda_runtime.h>
#include <cuda_fp16.h>
#include <math.h>
#include <stdint.h>

#define B_  32
#define L_  512
#define SD_ 17
#define AD_ 6
#define DM_ 384
#define NL_ 12
#define N2_ 32
#define LT_ 2048           // 4*L
#define EPS_ 1e-5f

typedef unsigned long long u64;

// ---------------- scratch (device globals; no allocations allowed) -------------
__device__ float  g_z  [B_*DM_*LT_];    // embed output (layer-0 input)
__device__ float  g_zt [B_*DM_*LT_];    // raw residual stream (pre-LN), in-place
__device__ __half g_xh [B_*DM_*LT_];    // gelu output, fp16 hi
__device__ __half g_xl [B_*DM_*LT_];    // gelu output, fp16 lo
__device__ __half g_wh [NL_*768*DM_];   // conv_w fp16 hi
__device__ __half g_wl [NL_*768*DM_];   // conv_w fp16 lo
__device__ float2 g_lam[NL_*DM_*N2_];
__device__ float2 g_cm [NL_*DM_*N2_];
__device__ float  g_sum[B_*LT_];        // LN partial sums (reset by last CTA)
__device__ float  g_sq [B_*LT_];
__device__ float  g_m  [B_*LT_];        // LN mean
__device__ float  g_r  [B_*LT_];        // LN rstd
__device__ int    g_cnt[B_*16];         // per-(b, l-tile) arrival counters

__device__ __forceinline__ uint32_t smem_u32(const void* p) {
    uint32_t a;
    asm("{ .reg .u64 t; cvta.to.shared.u64 t, %1; cvt.u32.u64 %0, t; }" : "=r"(a) : "l"(p));
    return a;
}
__device__ __forceinline__ void cpa16(uint32_t dst, const void* src) {
    asm volatile("cp.async.cg.shared.global [%0], [%1], 16;" :: "r"(dst), "l"(src) : "memory");
}
// ---- packed f32x2 helpers ----
__device__ __forceinline__ u64 pk2(float x, float y) {
    u64 r; asm("mov.b64 %0, {%1,%2};" : "=l"(r) : "f"(x), "f"(y)); return r;
}
__device__ __forceinline__ void upk2(u64 v, float& x, float& y) {
    asm("mov.b64 {%0,%1}, %2;" : "=f"(x), "=f"(y) : "l"(v));
}
__device__ __forceinline__ u64 fma2_(u64 a, u64 b, u64 c) {
    u64 d; asm("fma.rn.f32x2 %0, %1, %2, %3;" : "=l"(d) : "l"(a), "l"(b), "l"(c)); return d;
}
__device__ __forceinline__ u64 mul2_(u64 a, u64 b) {
    u64 d; asm("mul.rn.f32x2 %0, %1, %2;" : "=l"(d) : "l"(a), "l"(b)); return d;
}
__device__ __forceinline__ u64 add2_(u64 a, u64 b) {
    u64 d; asm("add.rn.f32x2 %0, %1, %2;" : "=l"(d) : "l"(a), "l"(b)); return d;
}

// ---------------- K0: per-layer S4D coefficient precompute ---------------------
__global__ void k_precompute(const float* __restrict__ log_dt,
                             const float* __restrict__ C_ri,
                             const float* __restrict__ log_A_real,
                             const float* __restrict__ A_imag) {
    int idx = blockIdx.x * blockDim.x + threadIdx.x;
    if (idx >= NL_*DM_*N2_) return;
    int h = (idx / N2_) % DM_;
    int i = idx / (N2_*DM_);
    float dt = expf(log_dt[i*DM_ + h]);
    float Ar = -expf(log_A_real[idx]);
    float Ai = A_imag[idx];
    float dr = Ar*dt, di = Ai*dt;
    float er = expf(dr);
    float lr = er*cosf(di), li = er*sinf(di);
    float exr = lr - 1.0f, exi = li;
    float den = Ar*Ar + Ai*Ai;
    float wr = (exr*Ar + exi*Ai)/den;
    float wi = (exi*Ar - exr*Ai)/den;
    float Cr = C_ri[idx*2+0], Ci = C_ri[idx*2+1];
    g_lam[idx] = make_float2(lr, li);
    g_cm[idx]  = make_float2(2.0f*(Cr*wr - Ci*wi), 2.0f*(Cr*wi + Ci*wr));
}

// ---------------- K0b: weight split fp32 -> fp16 hi/lo -------------------------
__global__ void k_prep_w(const float* __restrict__ conv_w) {
    int idx = blockIdx.x * blockDim.x + threadIdx.x;
    if (idx >= NL_*768*DM_) return;
    float v = conv_w[idx];
    __half h = __float2half_rn(v);
    g_wh[idx] = h;
    g_wl[idx] = __float2half_rn(v - __half2float(h));
}

// ---------------- K1: embedding + interleave into (B, DM, 4L) ------------------
__global__ void k_embed(const float* __restrict__ states,
                        const float* __restrict__ actions,
                        const float* __restrict__ rtg,
                        const float* __restrict__ ctg,
                        const int*   __restrict__ tsteps,
                        const float* __restrict__ W_es, const float* __restrict__ b_es,
                        const float* __restrict__ W_ea, const float* __restrict__ b_ea,
                        const float* __restrict__ W_er, const float* __restrict__ b_er,
                        const float* __restrict__ W_ec, const float* __restrict__ b_ec,
                        const float* __restrict__ E_t) {
    int bl = blockIdx.x;
    int b = bl / L_, l = bl % L_;
    int h = threadIdx.x;
    int t = tsteps[bl];
    float te = E_t[t*DM_ + h];
    float r = rtg[bl], c = ctg[bl];
    float er = fmaf(r, W_er[h], b_er[h]) + te;
    float ec = fmaf(c, W_ec[h], b_ec[h]) + te;
    float es = b_es[h] + te;
    #pragma unroll
    for (int s = 0; s < SD_; s++) es = fmaf(states[bl*SD_ + s], W_es[s*DM_ + h], es);
    float ea = b_ea[h] + te;
    #pragma unroll
    for (int s = 0; s < AD_; s++) ea = fmaf(actions[bl*AD_ + s], W_ea[s*DM_ + h], ea);
    float* zr = g_z + ((size_t)(b*DM_ + h))*LT_ + 4*l;
    zr[0] = er; zr[1] = ec; zr[2] = es; zr[3] = ea;
}

// ---------------- K2: S4D recurrence, 2 batch-streams/lane via f32x2 -----------
// Time-major transpose buffer bw[t][n] (row stride 34 u64): writer = contiguous
// STS.64; reducer = 16 conflict-free LDS.128 per lane. z broadcast reads 2 steps
// per LDS.128.
__global__ __launch_bounds__(128) void k_s4d(const float* __restrict__ Dskip,
                                             const float* __restrict__ ln_g,
                                             const float* __restrict__ ln_b,
                                             int layer, int prev) {
    __shared__ __align__(16) u64 buf[4][32][34];   // [t][n + 2 pad]
    __shared__ __align__(16) u64 zs [4][32];
    int wid  = threadIdx.x >> 5;
    int lane = threadIdx.x & 31;
    int gw = blockIdx.x*4 + wid;
    int h  = gw % DM_;
    int bq = gw / DM_;
    int b0 = bq*2, b1 = bq*2 + 1;
    int pidx = (layer*DM_ + h)*N2_ + lane;
    float2 LM = g_lam[pidx];
    float2 CM = g_cm[pidx];
    u64 LMx2  = pk2( LM.x,  LM.x);
    u64 LMy2  = pk2( LM.y,  LM.y);
    u64 nLMy2 = pk2(-LM.y, -LM.y);
    u64 CMx2  = pk2( CM.x,  CM.x);
    u64 nCMy2 = pk2(-CM.y, -CM.y);
    float D   = Dskip[layer*DM_ + h];
    float lng = 1.0f, lnb = 0.0f;
    const float* zsrc = prev ? g_zt : g_z;
    if (prev) { lng = ln_g[(layer-1)*DM_ + h]; lnb = ln_b[(layer-1)*DM_ + h]; }
    const float* z0r = zsrc + ((size_t)(b0*DM_ + h))*LT_;
    const float* z1r = zsrc + ((size_t)(b1*DM_ + h))*LT_;
    const float* m0r = g_m + (size_t)b0*LT_;
    const float* m1r = g_m + (size_t)b1*LT_;
    const float* r0r = g_r + (size_t)b0*LT_;
    const float* r1r = g_r + (size_t)b1*LT_;
    __half* xh0 = g_xh + ((size_t)(b0*DM_ + h))*LT_;
    __half* xl0 = g_xl + ((size_t)(b0*DM_ + h))*LT_;
    __half* xh1 = g_xh + ((size_t)(b1*DM_ + h))*LT_;
    __half* xl1 = g_xl + ((size_t)(b1*DM_ + h))*LT_;

    u64 sr = 0ULL, si = 0ULL;
    u64 (*bw)[34] = buf[wid];
    u64* zw = zs[wid];
    for (int lb = 0; lb < LT_; lb += 32) {
        int l = lb + lane;
        float z0 = z0r[l], z1 = z1r[l];
        if (prev) {
            z0 = fmaf((z0 - m0r[l]) * r0r[l], lng, lnb);
            z1 = fmaf((z1 - m1r[l]) * r1r[l], lng, lnb);
        }
        zw[lane] = pk2(z0, z1);
        __syncwarp();
        #pragma unroll
        for (int t = 0; t < 32; t += 2) {
            ulonglong2 zz = *(const ulonglong2*)&zw[t];    // 2 steps per LDS.128
            u64 nsr = fma2_(LMx2, sr, fma2_(nLMy2, si, zz.x));
            u64 nsi = fma2_(LMy2, sr, mul2_(LMx2, si));
            sr = nsr; si = nsi;
            bw[t][lane] = fma2_(CMx2, sr, mul2_(nCMy2, si));
            nsr = fma2_(LMx2, sr, fma2_(nLMy2, si, zz.y));
            nsi = fma2_(LMy2, sr, mul2_(LMx2, si));
            sr = nsr; si = nsi;
            bw[t+1][lane] = fma2_(CMx2, sr, mul2_(nCMy2, si));
        }
        __syncwarp();
        // reduce over states: lane owns t = lane, reads its contiguous row
        u64 a0 = 0ULL, a1 = 0ULL, a2 = 0ULL, a3 = 0ULL;
        #pragma unroll
        for (int k = 0; k < 8; k++) {
            ulonglong2 v0 = *(const ulonglong2*)&bw[lane][k*4    ];
            ulonglong2 v1 = *(const ulonglong2*)&bw[lane][k*4 + 2];
            a0 = add2_(a0, v0.x);
            a1 = add2_(a1, v0.y);
            a2 = add2_(a2, v1.x);
            a3 = add2_(a3, v1.y);
        }
        u64 acc = add2_(add2_(a0, a1), add2_(a2, a3));
        float y0, y1;
        upk2(acc, y0, y1);
        float yv0 = fmaf(D, z0, y0);
        float yv1 = fmaf(D, z1, y1);
        float ge0 = 0.5f * yv0 * (1.0f + erff(yv0 * 0.70710678118654752f));
        float ge1 = 0.5f * yv1 * (1.0f + erff(yv1 * 0.70710678118654752f));
        __half h0 = __float2half_rn(ge0);
        __half h1 = __float2half_rn(ge1);
        xh0[l] = h0; xl0[l] = __float2half_rn(ge0 - __half2float(h0));
        xh1[l] = h1; xl1[l] = __float2half_rn(ge1 - __half2float(h1));
        __syncwarp();
    }
}

// ---------------- K3: mma.sync fp16-split GEMM + GLU + residual + LN stats -----
#define BK_ 32
#define AP_ 40
#define BP_ 136
#define NCH_ (DM_/BK_)   // 12

struct Buf {
    __half aa_hi[64][AP_], aa_lo[64][AP_];
    __half ag_hi[64][AP_], ag_lo[64][AP_];
    __half bhi[BK_][BP_],  blo[BK_][BP_];
};
struct Epi {
    float gbuf[64][132];
    float st_s[128][16];
    float st_q[128][16];
};
struct SmemG {
    union { Buf buf[2]; Epi ep; };
};

__device__ __forceinline__ void ldmx4(uint32_t* r, uint32_t addr) {
    asm volatile("ldmatrix.sync.aligned.m8n8.x4.shared.b16 {%0,%1,%2,%3}, [%4];"
        : "=r"(r[0]), "=r"(r[1]), "=r"(r[2]), "=r"(r[3]) : "r"(addr));
}
__device__ __forceinline__ void ldmx4t(uint32_t* r, uint32_t addr) {
    asm volatile("ldmatrix.sync.aligned.m8n8.x4.trans.shared.b16 {%0,%1,%2,%3}, [%4];"
        : "=r"(r[0]), "=r"(r[1]), "=r"(r[2]), "=r"(r[3]) : "r"(addr));
}
__device__ __forceinline__ void mma16816(float* c, const uint32_t* a, uint32_t b0, uint32_t b1) {
    asm volatile("mma.sync.aligned.m16n8k16.row.col.f32.f16.f16.f32 "
        "{%0,%1,%2,%3}, {%4,%5,%6,%7}, {%8,%9}, {%0,%1,%2,%3};"
        : "+f"(c[0]), "+f"(c[1]), "+f"(c[2]), "+f"(c[3])
        : "r"(a[0]), "r"(a[1]), "r"(a[2]), "r"(a[3]), "r"(b0), "r"(b1));
}

__device__ __forceinline__ void load_chunk(Buf* bf, const __half* whL, const __half* wlL,
                                           const __half* xhB, const __half* xlB,
                                           int o0, int k0, int tid) {
    int row = tid >> 2, q = (tid & 3) * 8;
    size_t offA = (size_t)(o0 + row)*DM_ + k0 + q;
    size_t offG = (size_t)(384 + o0 + row)*DM_ + k0 + q;
    cpa16(smem_u32(&bf->aa_hi[row][q]), whL + offA);
    cpa16(smem_u32(&bf->aa_lo[row][q]), wlL + offA);
    cpa16(smem_u32(&bf->ag_hi[row][q]), whL + offG);
    cpa16(smem_u32(&bf->ag_lo[row][q]), wlL + offG);
    int br = tid >> 3, bq = (tid & 7) * 8;
    const __half* xh = xhB + (size_t)(k0 + br)*LT_;
    const __half* xl = xlB + (size_t)(k0 + br)*LT_;
    cpa16(smem_u32(&bf->bhi[br][bq     ]), xh + bq);
    cpa16(smem_u32(&bf->bhi[br][bq + 64]), xh + bq + 64);
    cpa16(smem_u32(&bf->blo[br][bq     ]), xl + bq);
    cpa16(smem_u32(&bf->blo[br][bq + 64]), xl + bq + 64);
}

__global__ __launch_bounds__(256, 2) void k_gemm_mma(const float* __restrict__ conv_b,
                                                     const float* __restrict__ ln_g,
                                                     const float* __restrict__ ln_b,
                                                     int layer, int prev) {
    extern __shared__ char dsm[];
    SmemG* sm = (SmemG*)dsm;
    __shared__ int lastflag;
    int tid = threadIdx.x;
    int l0 = blockIdx.x * 128;
    int o0 = blockIdx.y * 64;
    int b  = blockIdx.z;
    const __half* whL = g_wh + (size_t)layer*768*DM_;
    const __half* wlL = g_wl + (size_t)layer*768*DM_;
    const __half* xhB = g_xh + (size_t)b*DM_*LT_ + l0;
    const __half* xlB = g_xl + (size_t)b*DM_*LT_ + l0;
    const float*  cb  = conv_b + layer*768;

    int w = tid >> 5, lane = tid & 31;
    bool is_g = (w >= 4);
    int wl = w & 3;
    int m_off = (wl & 1) * 32;
    int n_off = (wl >> 1) * 64;

    float c[2][8][4];
    #pragma unroll
    for (int i = 0; i < 2; i++)
        #pragma unroll
        for (int j = 0; j < 8; j++)
            #pragma unroll
            for (int q = 0; q < 4; q++) c[i][j][q] = 0.0f;

    load_chunk(&sm->buf[0], whL, wlL, xhB, xlB, o0, 0, tid);
    asm volatile("cp.async.commit_group;" ::: "memory");

    for (int ch = 0; ch < NCH_; ch++) {
        if (ch + 1 < NCH_) {
            load_chunk(&sm->buf[(ch+1)&1], whL, wlL, xhB, xlB, o0, (ch+1)*BK_, tid);
            asm volatile("cp.async.commit_group;" ::: "memory");
            asm volatile("cp.async.wait_group 1;" ::: "memory");
        } else {
            asm volatile("cp.async.wait_group 0;" ::: "memory");
        }
        __syncthreads();
        Buf* bf = &sm->buf[ch & 1];
        const __half (*Ahi)[AP_] = is_g ? bf->ag_hi : bf->aa_hi;
        const __half (*Alo)[AP_] = is_g ? bf->ag_lo : bf->aa_lo;
        #pragma unroll
        for (int s = 0; s < 2; s++) {
            uint32_t ah[2][4], al[2][4];
            int arow = m_off + (lane & 15);
            int acol = s*16 + (lane >> 4)*8;
            #pragma unroll
            for (int mt = 0; mt < 2; mt++) {
                ldmx4 (ah[mt], smem_u32(&Ahi[arow + mt*16][acol]));
                ldmx4 (al[mt], smem_u32(&Alo[arow + mt*16][acol]));
            }
            int brow = s*16 + (lane & 15);
            #pragma unroll
            for (int g4 = 0; g4 < 4; g4++) {
                int bcol = n_off + g4*16 + (lane >> 4)*8;
                uint32_t bh[4], bl_[4];
                ldmx4t(bh,  smem_u32(&bf->bhi[brow][bcol]));
                ldmx4t(bl_, smem_u32(&bf->blo[brow][bcol]));
                #pragma unroll
                for (int hf = 0; hf < 2; hf++) {
                    int nt = g4*2 + hf;
                    uint32_t b0h = bh[hf*2],  b1h = bh[hf*2+1];
                    uint32_t b0l = bl_[hf*2], b1l = bl_[hf*2+1];
                    #pragma unroll
                    for (int mt = 0; mt < 2; mt++) {
                        mma16816(c[mt][nt], ah[mt], b0h, b1h);
                        mma16816(c[mt][nt], ah[mt], b0l, b1l);
                        mma16816(c[mt][nt], al[mt], b0h, b1h);
                    }
                }
            }
        }
        __syncthreads();
    }

    // ---- epilogue: g stash -> GLU + residual(+LN of prev) -> LN stats ----------
    if (is_g) {
        #pragma unroll
        for (int mt = 0; mt < 2; mt++)
            #pragma unroll
            for (int nt = 0; nt < 8; nt++) {
                int r  = m_off + mt*16 + (lane >> 2);
                int cc = n_off + nt*8 + (lane & 3)*2;
                *(float2*)&sm->ep.gbuf[r  ][cc] = make_float2(c[mt][nt][0], c[mt][nt][1]);
                *(float2*)&sm->ep.gbuf[r+8][cc] = make_float2(c[mt][nt][2], c[mt][nt][3]);
            }
    }
    __syncthreads();
    if (!is_g) {
        size_t bL = (size_t)b*LT_ + l0;
        const float* lngL = ln_g + (prev ? (layer-1)*DM_ : 0);
        const float* lnbL = ln_b + (prev ? (layer-1)*DM_ : 0);
        float ba[2][2], bg[2][2], lgv[2][2], lbv[2][2];
        #pragma unroll
        for (int mt = 0; mt < 2; mt++)
            #pragma unroll
            for (int rh = 0; rh < 2; rh++) {
                int o = o0 + m_off + mt*16 + (lane >> 2) + rh*8;
                ba[mt][rh] = cb[o]; bg[mt][rh] = cb[384 + o];
                lgv[mt][rh] = prev ? lngL[o] : 1.0f;
                lbv[mt][rh] = prev ? lnbL[o] : 0.0f;
            }
        int slot = (wl & 1)*8 + (lane >> 2);
        #pragma unroll
        for (int nt = 0; nt < 8; nt++) {
            int cc = n_off + nt*8 + (lane & 3)*2;
            float2 mv = make_float2(0.f, 0.f), rv = make_float2(1.f, 1.f);
            if (prev) {
                mv = *(const float2*)&g_m[bL + cc];
                rv = *(const float2*)&g_r[bL + cc];
            }
            float s0 = 0.f, s1 = 0.f, q0 = 0.f, q1 = 0.f;
            #pragma unroll
            for (int mt = 0; mt < 2; mt++)
                #pragma unroll
                for (int rh = 0; rh < 2; rh++) {
                    int row = m_off + mt*16 + (lane >> 2) + rh*8;
                    int o   = o0 + row;
                    float2 gv = *(float2*)&sm->ep.gbuf[row][cc];
                    size_t gix = ((size_t)(b*DM_ + o))*LT_ + l0 + cc;
                    float2 res;
                    if (prev) {
                        float2 raw = *(const float2*)&g_zt[gix];
                        res.x = fmaf((raw.x - mv.x) * rv.x, lgv[mt][rh], lbv[mt][rh]);
                        res.y = fmaf((raw.y - mv.y) * rv.y, lgv[mt][rh], lbv[mt][rh]);
                    } else {
                        res = *(const float2*)&g_z[gix];
                    }
                    float a0 = c[mt][nt][rh*2+0] + ba[mt][rh];
                    float a1 = c[mt][nt][rh*2+1] + ba[mt][rh];
                    float g0 = gv.x + bg[mt][rh], g1 = gv.y + bg[mt][rh];
                    float sg0 = 1.0f / (1.0f + expf(-g0));
                    float sg1 = 1.0f / (1.0f + expf(-g1));
                    float v0 = fmaf(a0, sg0, res.x);
                    float v1 = fmaf(a1, sg1, res.y);
                    *(float2*)&g_zt[gix] = make_float2(v0, v1);
                    s0 += v0; q0 = fmaf(v0, v0, q0);
                    s1 += v1; q1 = fmaf(v1, v1, q1);
                }
            sm->ep.st_s[cc  ][slot] = s0;
            sm->ep.st_s[cc+1][slot] = s1;
            sm->ep.st_q[cc  ][slot] = q0;
            sm->ep.st_q[cc+1][slot] = q1;
        }
    }
    __syncthreads();
    {
        int col = tid >> 1, which = tid & 1;
        const float* arr = which ? &sm->ep.st_q[col][0] : &sm->ep.st_s[col][0];
        float s = 0.f;
        #pragma unroll
        for (int k = 0; k < 16; k++) s += arr[k];
        float* dst = which ? g_sq : g_sum;
        atomicAdd(dst + (size_t)b*LT_ + l0 + col, s);
    }
    // ---- fused stat finalize: last CTA of this (b, l-tile) computes m/rstd -----
    __threadfence();
    if (tid == 0) {
        int old = atomicAdd(&g_cnt[b*16 + blockIdx.x], 1);
        lastflag = (old == (int)gridDim.y - 1);
    }
    __syncthreads();
    if (lastflag) {
        if (tid < 128) {
            size_t ix = (size_t)b*LT_ + l0 + tid;
            float s = __ldcg(&g_sum[ix]);
            float q = __ldcg(&g_sq[ix]);
            float m = s * (1.0f/DM_);
            float v = q * (1.0f/DM_) - m*m;
            g_m[ix] = m;
            g_r[ix] = rsqrtf(v + EPS_);
            g_sum[ix] = 0.0f;
            g_sq[ix]  = 0.0f;
        } else if (tid == 128) {
            g_cnt[b*16 + blockIdx.x] = 0;
        }
    }
}

// ---------------- K5: output projections (normalize final z on the fly) --------
__global__ __launch_bounds__(256) void k_final(const float* __restrict__ W_pa,
                                               const float* __restrict__ b_pa,
                                               const float* __restrict__ W_ps,
                                               const float* __restrict__ b_ps,
                                               const float* __restrict__ ln_g,
                                               const float* __restrict__ ln_b,
                                               float* __restrict__ out) {
    __shared__ float zt[DM_][32];
    int b  = blockIdx.y;
    int l0 = blockIdx.x * 8;
    int p  = threadIdx.x & 31;
    int hg = threadIdx.x >> 5;
    size_t base = (size_t)b*LT_ + l0*4;
    float m = g_m[base + p];
    float r = g_r[base + p];
    const float* lg = ln_g + (NL_-1)*DM_;
    const float* lb = ln_b + (NL_-1)*DM_;
    for (int h = hg; h < DM_; h += 8) {
        float v = g_zt[((size_t)(b*DM_ + h))*LT_ + l0*4 + p];
        zt[h][p] = fmaf((v - m) * r, lg[h], lb[h]);
    }
    __syncthreads();
    int t = threadIdx.x;
    if (t < 8*(SD_ + AD_)) {
        int li = t / (SD_ + AD_);
        int o  = t % (SD_ + AD_);
        int l  = l0 + li;
        if (o < SD_) {
            int pp = li*4 + 3;
            float acc = b_ps[o];
            #pragma unroll 8
            for (int h = 0; h < DM_; h++) acc = fmaf(zt[h][pp], W_ps[h*SD_ + o], acc);
            out[((size_t)(b*L_ + l))*SD_ + o] = acc;
        } else {
            int o2 = o - SD_;
            int pp = li*4 + 2;
            float acc = b_pa[o2];
            #pragma unroll 8
            for (int h = 0; h < DM_; h++) acc = fmaf(zt[h][pp], W_pa[h*AD_ + o2], acc);
            out[(size_t)B_*L_*SD_ + ((size_t)(b*L_ + l))*AD_ + o2] = acc;
        }
    }
}

// ---------------- launch --------------------------------------------------------
extern "C" void kernel_launch(void* const* d_in, const int* in_sizes, int n_in,
                              void* d_out, int out_size) {
    const float* states     = (const float*)d_in[0];
    const float* actions    = (const float*)d_in[1];
    const float* rtg        = (const float*)d_in[2];
    const float* ctg        = (const float*)d_in[3];
    const int*   tsteps     = (const int*  )d_in[4];
    const float* W_es       = (const float*)d_in[5];
    const float* b_es       = (const float*)d_in[6];
    const float* W_ea       = (const float*)d_in[7];
    const float* b_ea       = (const float*)d_in[8];
    const float* W_er       = (const float*)d_in[9];
    const float* b_er       = (const float*)d_in[10];
    const float* W_ec       = (const float*)d_in[11];
    const float* b_ec       = (const float*)d_in[12];
    const float* E_t        = (const float*)d_in[13];
    const float* log_dt     = (const float*)d_in[14];
    const float* C_ri       = (const float*)d_in[15];
    const float* log_A_real = (const float*)d_in[16];
    const float* A_imag     = (const float*)d_in[17];
    const float* D_skip     = (const float*)d_in[18];
    const float* conv_w     = (const float*)d_in[19];
    const float* conv_b     = (const float*)d_in[20];
    const float* ln_g       = (const float*)d_in[21];
    const float* ln_b       = (const float*)d_in[22];
    const float* W_pa       = (const float*)d_in[23];
    const float* b_pa       = (const float*)d_in[24];
    const float* W_ps       = (const float*)d_in[25];
    const float* b_ps       = (const float*)d_in[26];

    cudaFuncSetAttribute(k_gemm_mma, cudaFuncAttributeMaxDynamicSharedMemorySize,
                         (int)sizeof(SmemG));

    k_precompute<<<(NL_*DM_*N2_ + 255)/256, 256>>>(log_dt, C_ri, log_A_real, A_imag);
    k_prep_w<<<(NL_*768*DM_ + 255)/256, 256>>>(conv_w);
    k_embed<<<B_*L_, DM_>>>(states, actions, rtg, ctg, tsteps,
                            W_es, b_es, W_ea, b_ea, W_er, b_er, W_ec, b_ec, E_t);
    for (int i = 0; i < NL_; i++) {
        int prev = (i > 0) ? 1 : 0;
        k_s4d<<<(DM_*(B_/2))/4, 128>>>(D_skip, ln_g, ln_b, i, prev);
        dim3 g3(LT_/128, DM_/64, B_);
        k_gemm_mma<<<g3, 256, sizeof(SmemG)>>>(conv_b, ln_g, ln_b, i, prev);
    }
    dim3 g5(L_/8, B_);
    k_final<<<g5, 256>>>(W_pa, b_pa, W_ps, b_ps, ln_g, ln_b, (float*)d_out);
}

// round 10
// speedup vs baseline: 1.1430x; 1.1137x over previous
#include <cuda_runtime.h>
#include <cuda_fp16.h>
#include <math.h>
#include <stdint.h>

#define B_  32
#define L_  512
#define SD_ 17
#define AD_ 6
#define DM_ 384
#define NL_ 12
#define N2_ 32
#define LT_ 2048           // 4*L
#define EPS_ 1e-5f

typedef unsigned long long u64;

// ---------------- scratch (device globals; no allocations allowed) -------------
__device__ float  g_z  [B_*DM_*LT_];    // embed output (layer-0 input)
__device__ float  g_zt [B_*DM_*LT_];    // raw residual stream (pre-LN), in-place
__device__ __half g_xh [B_*DM_*LT_];    // gelu output, fp16
__device__ __half g_wh [NL_*768*DM_];   // conv_w fp16 hi
__device__ __half g_wl [NL_*768*DM_];   // conv_w fp16 lo
__device__ float2 g_lam[NL_*DM_*N2_];
__device__ float2 g_cm [NL_*DM_*N2_];
__device__ float  g_sum[B_*LT_];        // LN partial sums (reset by last CTA)
__device__ float  g_sq [B_*LT_];
__device__ float  g_m  [B_*LT_];        // LN mean
__device__ float  g_r  [B_*LT_];        // LN rstd
__device__ int    g_cnt[B_*16];         // per-(b, l-tile) arrival counters

__device__ __forceinline__ uint32_t smem_u32(const void* p) {
    uint32_t a;
    asm("{ .reg .u64 t; cvta.to.shared.u64 t, %1; cvt.u32.u64 %0, t; }" : "=r"(a) : "l"(p));
    return a;
}
__device__ __forceinline__ void cpa16(uint32_t dst, const void* src) {
    asm volatile("cp.async.cg.shared.global [%0], [%1], 16;" :: "r"(dst), "l"(src) : "memory");
}
// ---- packed f32x2 helpers ----
__device__ __forceinline__ u64 pk2(float x, float y) {
    u64 r; asm("mov.b64 %0, {%1,%2};" : "=l"(r) : "f"(x), "f"(y)); return r;
}
__device__ __forceinline__ void upk2(u64 v, float& x, float& y) {
    asm("mov.b64 {%0,%1}, %2;" : "=f"(x), "=f"(y) : "l"(v));
}
__device__ __forceinline__ u64 fma2_(u64 a, u64 b, u64 c) {
    u64 d; asm("fma.rn.f32x2 %0, %1, %2, %3;" : "=l"(d) : "l"(a), "l"(b), "l"(c)); return d;
}
__device__ __forceinline__ u64 mul2_(u64 a, u64 b) {
    u64 d; asm("mul.rn.f32x2 %0, %1, %2;" : "=l"(d) : "l"(a), "l"(b)); return d;
}
__device__ __forceinline__ u64 add2_(u64 a, u64 b) {
    u64 d; asm("add.rn.f32x2 %0, %1, %2;" : "=l"(d) : "l"(a), "l"(b)); return d;
}

// ---------------- K0: per-layer S4D coefficient precompute ---------------------
__global__ void k_precompute(const float* __restrict__ log_dt,
                             const float* __restrict__ C_ri,
                             const float* __restrict__ log_A_real,
                             const float* __restrict__ A_imag) {
    int idx = blockIdx.x * blockDim.x + threadIdx.x;
    if (idx >= NL_*DM_*N2_) return;
    int h = (idx / N2_) % DM_;
    int i = idx / (N2_*DM_);
    float dt = expf(log_dt[i*DM_ + h]);
    float Ar = -expf(log_A_real[idx]);
    float Ai = A_imag[idx];
    float dr = Ar*dt, di = Ai*dt;
    float er = expf(dr);
    float lr = er*cosf(di), li = er*sinf(di);
    float exr = lr - 1.0f, exi = li;
    float den = Ar*Ar + Ai*Ai;
    float wr = (exr*Ar + exi*Ai)/den;
    float wi = (exi*Ar - exr*Ai)/den;
    float Cr = C_ri[idx*2+0], Ci = C_ri[idx*2+1];
    g_lam[idx] = make_float2(lr, li);
    g_cm[idx]  = make_float2(2.0f*(Cr*wr - Ci*wi), 2.0f*(Cr*wi + Ci*wr));
}

// ---------------- K0b: weight split fp32 -> fp16 hi/lo -------------------------
__global__ void k_prep_w(const float* __restrict__ conv_w) {
    int idx = blockIdx.x * blockDim.x + threadIdx.x;
    if (idx >= NL_*768*DM_) return;
    float v = conv_w[idx];
    __half h = __float2half_rn(v);
    g_wh[idx] = h;
    g_wl[idx] = __float2half_rn(v - __half2float(h));
}

// ---------------- K1: embedding + interleave into (B, DM, 4L) ------------------
__global__ void k_embed(const float* __restrict__ states,
                        const float* __restrict__ actions,
                        const float* __restrict__ rtg,
                        const float* __restrict__ ctg,
                        const int*   __restrict__ tsteps,
                        const float* __restrict__ W_es, const float* __restrict__ b_es,
                        const float* __restrict__ W_ea, const float* __restrict__ b_ea,
                        const float* __restrict__ W_er, const float* __restrict__ b_er,
                        const float* __restrict__ W_ec, const float* __restrict__ b_ec,
                        const float* __restrict__ E_t) {
    int bl = blockIdx.x;
    int b = bl / L_, l = bl % L_;
    int h = threadIdx.x;
    int t = tsteps[bl];
    float te = E_t[t*DM_ + h];
    float r = rtg[bl], c = ctg[bl];
    float er = fmaf(r, W_er[h], b_er[h]) + te;
    float ec = fmaf(c, W_ec[h], b_ec[h]) + te;
    float es = b_es[h] + te;
    #pragma unroll
    for (int s = 0; s < SD_; s++) es = fmaf(states[bl*SD_ + s], W_es[s*DM_ + h], es);
    float ea = b_ea[h] + te;
    #pragma unroll
    for (int s = 0; s < AD_; s++) ea = fmaf(actions[bl*AD_ + s], W_ea[s*DM_ + h], ea);
    float* zr = g_z + ((size_t)(b*DM_ + h))*LT_ + 4*l;
    zr[0] = er; zr[1] = ec; zr[2] = es; zr[3] = ea;
}

// ---------------- K2: S4D recurrence, 2 batch-streams/lane via f32x2 -----------
__global__ __launch_bounds__(128) void k_s4d(const float* __restrict__ Dskip,
                                             const float* __restrict__ ln_g,
                                             const float* __restrict__ ln_b,
                                             int layer, int prev) {
    __shared__ __align__(16) u64 buf[4][32][34];   // [t][n + 2 pad]
    __shared__ __align__(16) u64 zs [4][32];
    int wid  = threadIdx.x >> 5;
    int lane = threadIdx.x & 31;
    int gw = blockIdx.x*4 + wid;
    int h  = gw % DM_;
    int bq = gw / DM_;
    int b0 = bq*2, b1 = bq*2 + 1;
    int pidx = (layer*DM_ + h)*N2_ + lane;
    float2 LM = g_lam[pidx];
    float2 CM = g_cm[pidx];
    u64 LMx2  = pk2( LM.x,  LM.x);
    u64 LMy2  = pk2( LM.y,  LM.y);
    u64 nLMy2 = pk2(-LM.y, -LM.y);
    u64 CMx2  = pk2( CM.x,  CM.x);
    u64 nCMy2 = pk2(-CM.y, -CM.y);
    float D   = Dskip[layer*DM_ + h];
    float lng = 1.0f, lnb = 0.0f;
    const float* zsrc = prev ? g_zt : g_z;
    if (prev) { lng = ln_g[(layer-1)*DM_ + h]; lnb = ln_b[(layer-1)*DM_ + h]; }
    const float* z0r = zsrc + ((size_t)(b0*DM_ + h))*LT_;
    const float* z1r = zsrc + ((size_t)(b1*DM_ + h))*LT_;
    const float* m0r = g_m + (size_t)b0*LT_;
    const float* m1r = g_m + (size_t)b1*LT_;
    const float* r0r = g_r + (size_t)b0*LT_;
    const float* r1r = g_r + (size_t)b1*LT_;
    __half* xh0 = g_xh + ((size_t)(b0*DM_ + h))*LT_;
    __half* xh1 = g_xh + ((size_t)(b1*DM_ + h))*LT_;

    u64 sr = 0ULL, si = 0ULL;
    u64 (*bw)[34] = buf[wid];
    u64* zw = zs[wid];
    for (int lb = 0; lb < LT_; lb += 32) {
        int l = lb + lane;
        float z0 = z0r[l], z1 = z1r[l];
        if (prev) {
            z0 = fmaf((z0 - m0r[l]) * r0r[l], lng, lnb);
            z1 = fmaf((z1 - m1r[l]) * r1r[l], lng, lnb);
        }
        zw[lane] = pk2(z0, z1);
        __syncwarp();
        #pragma unroll
        for (int t = 0; t < 32; t += 2) {
            ulonglong2 zz = *(const ulonglong2*)&zw[t];
            u64 nsr = fma2_(LMx2, sr, fma2_(nLMy2, si, zz.x));
            u64 nsi = fma2_(LMy2, sr, mul2_(LMx2, si));
            sr = nsr; si = nsi;
            bw[t][lane] = fma2_(CMx2, sr, mul2_(nCMy2, si));
            nsr = fma2_(LMx2, sr, fma2_(nLMy2, si, zz.y));
            nsi = fma2_(LMy2, sr, mul2_(LMx2, si));
            sr = nsr; si = nsi;
            bw[t+1][lane] = fma2_(CMx2, sr, mul2_(nCMy2, si));
        }
        __syncwarp();
        u64 a0 = 0ULL, a1 = 0ULL, a2 = 0ULL, a3 = 0ULL;
        #pragma unroll
        for (int k = 0; k < 8; k++) {
            ulonglong2 v0 = *(const ulonglong2*)&bw[lane][k*4    ];
            ulonglong2 v1 = *(const ulonglong2*)&bw[lane][k*4 + 2];
            a0 = add2_(a0, v0.x);
            a1 = add2_(a1, v0.y);
            a2 = add2_(a2, v1.x);
            a3 = add2_(a3, v1.y);
        }
        u64 acc = add2_(add2_(a0, a1), add2_(a2, a3));
        float y0, y1;
        upk2(acc, y0, y1);
        float yv0 = fmaf(D, z0, y0);
        float yv1 = fmaf(D, z1, y1);
        float ge0 = 0.5f * yv0 * (1.0f + erff(yv0 * 0.70710678118654752f));
        float ge1 = 0.5f * yv1 * (1.0f + erff(yv1 * 0.70710678118654752f));
        xh0[l] = __float2half_rn(ge0);
        xh1[l] = __float2half_rn(ge1);
        __syncwarp();
    }
}

// ---------------- K3: 2-term mma.sync GEMM + GLU + residual + LN stats ---------
// D = (w_hi + w_lo) * x_fp16  (weights exact, activations fp16)
#define BK_ 32
#define AP_ 40
#define BP_ 136
#define NCH_ (DM_/BK_)   // 12

struct Buf {
    __half aa_hi[64][AP_], aa_lo[64][AP_];
    __half ag_hi[64][AP_], ag_lo[64][AP_];
    __half bhi[BK_][BP_];
};
struct Epi {
    float gbuf[64][132];
    float st_s[128][16];
    float st_q[128][16];
};
struct SmemG {
    union { Buf buf[2]; Epi ep; };
};

__device__ __forceinline__ void ldmx4(uint32_t* r, uint32_t addr) {
    asm volatile("ldmatrix.sync.aligned.m8n8.x4.shared.b16 {%0,%1,%2,%3}, [%4];"
        : "=r"(r[0]), "=r"(r[1]), "=r"(r[2]), "=r"(r[3]) : "r"(addr));
}
__device__ __forceinline__ void ldmx4t(uint32_t* r, uint32_t addr) {
    asm volatile("ldmatrix.sync.aligned.m8n8.x4.trans.shared.b16 {%0,%1,%2,%3}, [%4];"
        : "=r"(r[0]), "=r"(r[1]), "=r"(r[2]), "=r"(r[3]) : "r"(addr));
}
__device__ __forceinline__ void mma16816(float* c, const uint32_t* a, uint32_t b0, uint32_t b1) {
    asm volatile("mma.sync.aligned.m16n8k16.row.col.f32.f16.f16.f32 "
        "{%0,%1,%2,%3}, {%4,%5,%6,%7}, {%8,%9}, {%0,%1,%2,%3};"
        : "+f"(c[0]), "+f"(c[1]), "+f"(c[2]), "+f"(c[3])
        : "r"(a[0]), "r"(a[1]), "r"(a[2]), "r"(a[3]), "r"(b0), "r"(b1));
}

__device__ __forceinline__ void load_chunk(Buf* bf, const __half* whL, const __half* wlL,
                                           const __half* xhB, int o0, int k0, int tid) {
    int row = tid >> 2, q = (tid & 3) * 8;
    size_t offA = (size_t)(o0 + row)*DM_ + k0 + q;
    size_t offG = (size_t)(384 + o0 + row)*DM_ + k0 + q;
    cpa16(smem_u32(&bf->aa_hi[row][q]), whL + offA);
    cpa16(smem_u32(&bf->aa_lo[row][q]), wlL + offA);
    cpa16(smem_u32(&bf->ag_hi[row][q]), whL + offG);
    cpa16(smem_u32(&bf->ag_lo[row][q]), wlL + offG);
    int br = tid >> 3, bq = (tid & 7) * 8;
    const __half* xh = xhB + (size_t)(k0 + br)*LT_;
    cpa16(smem_u32(&bf->bhi[br][bq     ]), xh + bq);
    cpa16(smem_u32(&bf->bhi[br][bq + 64]), xh + bq + 64);
}

__global__ __launch_bounds__(256, 2) void k_gemm_mma(const float* __restrict__ conv_b,
                                                     const float* __restrict__ ln_g,
                                                     const float* __restrict__ ln_b,
                                                     int layer, int prev) {
    extern __shared__ char dsm[];
    SmemG* sm = (SmemG*)dsm;
    __shared__ int lastflag;
    int tid = threadIdx.x;
    int l0 = blockIdx.x * 128;
    int o0 = blockIdx.y * 64;
    int b  = blockIdx.z;
    const __half* whL = g_wh + (size_t)layer*768*DM_;
    const __half* wlL = g_wl + (size_t)layer*768*DM_;
    const __half* xhB = g_xh + (size_t)b*DM_*LT_ + l0;
    const float*  cb  = conv_b + layer*768;

    int w = tid >> 5, lane = tid & 31;
    bool is_g = (w >= 4);
    int wl = w & 3;
    int m_off = (wl & 1) * 32;
    int n_off = (wl >> 1) * 64;

    float c[2][8][4];
    #pragma unroll
    for (int i = 0; i < 2; i++)
        #pragma unroll
        for (int j = 0; j < 8; j++)
            #pragma unroll
            for (int q = 0; q < 4; q++) c[i][j][q] = 0.0f;

    load_chunk(&sm->buf[0], whL, wlL, xhB, o0, 0, tid);
    asm volatile("cp.async.commit_group;" ::: "memory");

    for (int ch = 0; ch < NCH_; ch++) {
        if (ch + 1 < NCH_) {
            load_chunk(&sm->buf[(ch+1)&1], whL, wlL, xhB, o0, (ch+1)*BK_, tid);
            asm volatile("cp.async.commit_group;" ::: "memory");
            asm volatile("cp.async.wait_group 1;" ::: "memory");
        } else {
            asm volatile("cp.async.wait_group 0;" ::: "memory");
        }
        __syncthreads();
        Buf* bf = &sm->buf[ch & 1];
        const __half (*Ahi)[AP_] = is_g ? bf->ag_hi : bf->aa_hi;
        const __half (*Alo)[AP_] = is_g ? bf->ag_lo : bf->aa_lo;
        #pragma unroll
        for (int s = 0; s < 2; s++) {
            uint32_t ah[2][4], al[2][4];
            int arow = m_off + (lane & 15);
            int acol = s*16 + (lane >> 4)*8;
            #pragma unroll
            for (int mt = 0; mt < 2; mt++) {
                ldmx4 (ah[mt], smem_u32(&Ahi[arow + mt*16][acol]));
                ldmx4 (al[mt], smem_u32(&Alo[arow + mt*16][acol]));
            }
            int brow = s*16 + (lane & 15);
            #pragma unroll
            for (int g4 = 0; g4 < 4; g4++) {
                int bcol = n_off + g4*16 + (lane >> 4)*8;
                uint32_t bh[4];
                ldmx4t(bh, smem_u32(&bf->bhi[brow][bcol]));
                #pragma unroll
                for (int hf = 0; hf < 2; hf++) {
                    int nt = g4*2 + hf;
                    uint32_t b0h = bh[hf*2], b1h = bh[hf*2+1];
                    #pragma unroll
                    for (int mt = 0; mt < 2; mt++) {
                        mma16816(c[mt][nt], ah[mt], b0h, b1h);
                        mma16816(c[mt][nt], al[mt], b0h, b1h);
                    }
                }
            }
        }
        __syncthreads();
    }

    // ---- epilogue: g stash -> GLU + residual(+LN of prev) -> LN stats ----------
    if (is_g) {
        #pragma unroll
        for (int mt = 0; mt < 2; mt++)
            #pragma unroll
            for (int nt = 0; nt < 8; nt++) {
                int r  = m_off + mt*16 + (lane >> 2);
                int cc = n_off + nt*8 + (lane & 3)*2;
                *(float2*)&sm->ep.gbuf[r  ][cc] = make_float2(c[mt][nt][0], c[mt][nt][1]);
                *(float2*)&sm->ep.gbuf[r+8][cc] = make_float2(c[mt][nt][2], c[mt][nt][3]);
            }
    }
    __syncthreads();
    if (!is_g) {
        size_t bL = (size_t)b*LT_ + l0;
        const float* lngL = ln_g + (prev ? (layer-1)*DM_ : 0);
        const float* lnbL = ln_b + (prev ? (layer-1)*DM_ : 0);
        float ba[2][2], bg[2][2], lgv[2][2], lbv[2][2];
        #pragma unroll
        for (int mt = 0; mt < 2; mt++)
            #pragma unroll
            for (int rh = 0; rh < 2; rh++) {
                int o = o0 + m_off + mt*16 + (lane >> 2) + rh*8;
                ba[mt][rh] = cb[o]; bg[mt][rh] = cb[384 + o];
                lgv[mt][rh] = prev ? lngL[o] : 1.0f;
                lbv[mt][rh] = prev ? lnbL[o] : 0.0f;
            }
        int slot = (wl & 1)*8 + (lane >> 2);
        #pragma unroll
        for (int nt = 0; nt < 8; nt++) {
            int cc = n_off + nt*8 + (lane & 3)*2;
            float2 mv = make_float2(0.f, 0.f), rv = make_float2(1.f, 1.f);
            if (prev) {
                mv = *(const float2*)&g_m[bL + cc];
                rv = *(const float2*)&g_r[bL + cc];
            }
            float s0 = 0.f, s1 = 0.f, q0 = 0.f, q1 = 0.f;
            #pragma unroll
            for (int mt = 0; mt < 2; mt++)
                #pragma unroll
                for (int rh = 0; rh < 2; rh++) {
                    int row = m_off + mt*16 + (lane >> 2) + rh*8;
                    int o   = o0 + row;
                    float2 gv = *(float2*)&sm->ep.gbuf[row][cc];
                    size_t gix = ((size_t)(b*DM_ + o))*LT_ + l0 + cc;
                    float2 res;
                    if (prev) {
                        float2 raw = *(const float2*)&g_zt[gix];
                        res.x = fmaf((raw.x - mv.x) * rv.x, lgv[mt][rh], lbv[mt][rh]);
                        res.y = fmaf((raw.y - mv.y) * rv.y, lgv[mt][rh], lbv[mt][rh]);
                    } else {
                        res = *(const float2*)&g_z[gix];
                    }
                    float a0 = c[mt][nt][rh*2+0] + ba[mt][rh];
                    float a1 = c[mt][nt][rh*2+1] + ba[mt][rh];
                    float g0 = gv.x + bg[mt][rh], g1 = gv.y + bg[mt][rh];
                    float sg0 = 1.0f / (1.0f + expf(-g0));
                    float sg1 = 1.0f / (1.0f + expf(-g1));
                    float v0 = fmaf(a0, sg0, res.x);
                    float v1 = fmaf(a1, sg1, res.y);
                    *(float2*)&g_zt[gix] = make_float2(v0, v1);
                    s0 += v0; q0 = fmaf(v0, v0, q0);
                    s1 += v1; q1 = fmaf(v1, v1, q1);
                }
            sm->ep.st_s[cc  ][slot] = s0;
            sm->ep.st_s[cc+1][slot] = s1;
            sm->ep.st_q[cc  ][slot] = q0;
            sm->ep.st_q[cc+1][slot] = q1;
        }
    }
    __syncthreads();
    {
        int col = tid >> 1, which = tid & 1;
        const float* arr = which ? &sm->ep.st_q[col][0] : &sm->ep.st_s[col][0];
        float s = 0.f;
        #pragma unroll
        for (int k = 0; k < 16; k++) s += arr[k];
        float* dst = which ? g_sq : g_sum;
        atomicAdd(dst + (size_t)b*LT_ + l0 + col, s);
    }
    // ---- fused stat finalize: last CTA of this (b, l-tile) computes m/rstd -----
    __threadfence();
    if (tid == 0) {
        int old = atomicAdd(&g_cnt[b*16 + blockIdx.x], 1);
        lastflag = (old == (int)gridDim.y - 1);
    }
    __syncthreads();
    if (lastflag) {
        if (tid < 128) {
            size_t ix = (size_t)b*LT_ + l0 + tid;
            float s = __ldcg(&g_sum[ix]);
            float q = __ldcg(&g_sq[ix]);
            float m = s * (1.0f/DM_);
            float v = q * (1.0f/DM_) - m*m;
            g_m[ix] = m;
            g_r[ix] = rsqrtf(v + EPS_);
            g_sum[ix] = 0.0f;
            g_sq[ix]  = 0.0f;
        } else if (tid == 128) {
            g_cnt[b*16 + blockIdx.x] = 0;
        }
    }
}

// ---------------- K5: output projections (normalize final z on the fly) --------
__global__ __launch_bounds__(256) void k_final(const float* __restrict__ W_pa,
                                               const float* __restrict__ b_pa,
                                               const float* __restrict__ W_ps,
                                               const float* __restrict__ b_ps,
                                               const float* __restrict__ ln_g,
                                               const float* __restrict__ ln_b,
                                               float* __restrict__ out) {
    __shared__ float zt[DM_][32];
    int b  = blockIdx.y;
    int l0 = blockIdx.x * 8;
    int p  = threadIdx.x & 31;
    int hg = threadIdx.x >> 5;
    size_t base = (size_t)b*LT_ + l0*4;
    float m = g_m[base + p];
    float r = g_r[base + p];
    const float* lg = ln_g + (NL_-1)*DM_;
    const float* lb = ln_b + (NL_-1)*DM_;
    for (int h = hg; h < DM_; h += 8) {
        float v = g_zt[((size_t)(b*DM_ + h))*LT_ + l0*4 + p];
        zt[h][p] = fmaf((v - m) * r, lg[h], lb[h]);
    }
    __syncthreads();
    int t = threadIdx.x;
    if (t < 8*(SD_ + AD_)) {
        int li = t / (SD_ + AD_);
        int o  = t % (SD_ + AD_);
        int l  = l0 + li;
        if (o < SD_) {
            int pp = li*4 + 3;
            float acc = b_ps[o];
            #pragma unroll 8
            for (int h = 0; h < DM_; h++) acc = fmaf(zt[h][pp], W_ps[h*SD_ + o], acc);
            out[((size_t)(b*L_ + l))*SD_ + o] = acc;
        } else {
            int o2 = o - SD_;
            int pp = li*4 + 2;
            float acc = b_pa[o2];
            #pragma unroll 8
            for (int h = 0; h < DM_; h++) acc = fmaf(zt[h][pp], W_pa[h*AD_ + o2], acc);
            out[(size_t)B_*L_*SD_ + ((size_t)(b*L_ + l))*AD_ + o2] = acc;
        }
    }
}

// ---------------- launch --------------------------------------------------------
extern "C" void kernel_launch(void* const* d_in, const int* in_sizes, int n_in,
                              void* d_out, int out_size) {
    const float* states     = (const float*)d_in[0];
    const float* actions    = (const float*)d_in[1];
    const float* rtg        = (const float*)d_in[2];
    const float* ctg        = (const float*)d_in[3];
    const int*   tsteps     = (const int*  )d_in[4];
    const float* W_es       = (const float*)d_in[5];
    const float* b_es       = (const float*)d_in[6];
    const float* W_ea       = (const float*)d_in[7];
    const float* b_ea       = (const float*)d_in[8];
    const float* W_er       = (const float*)d_in[9];
    const float* b_er       = (const float*)d_in[10];
    const float* W_ec       = (const float*)d_in[11];
    const float* b_ec       = (const float*)d_in[12];
    const float* E_t        = (const float*)d_in[13];
    const float* log_dt     = (const float*)d_in[14];
    const float* C_ri       = (const float*)d_in[15];
    const float* log_A_real = (const float*)d_in[16];
    const float* A_imag     = (const float*)d_in[17];
    const float* D_skip     = (const float*)d_in[18];
    const float* conv_w     = (const float*)d_in[19];
    const float* conv_b     = (const float*)d_in[20];
    const float* ln_g       = (const float*)d_in[21];
    const float* ln_b       = (const float*)d_in[22];
    const float* W_pa       = (const float*)d_in[23];
    const float* b_pa       = (const float*)d_in[24];
    const float* W_ps       = (const float*)d_in[25];
    const float* b_ps       = (const float*)d_in[26];

    cudaFuncSetAttribute(k_gemm_mma, cudaFuncAttributeMaxDynamicSharedMemorySize,
                         (int)sizeof(SmemG));

    k_precompute<<<(NL_*DM_*N2_ + 255)/256, 256>>>(log_dt, C_ri, log_A_real, A_imag);
    k_prep_w<<<(NL_*768*DM_ + 255)/256, 256>>>(conv_w);
    k_embed<<<B_*L_, DM_>>>(states, actions, rtg, ctg, tsteps,
                            W_es, b_es, W_ea, b_ea, W_er, b_er, W_ec, b_ec, E_t);
    for (int i = 0; i < NL_; i++) {
        int prev = (i > 0) ? 1 : 0;
        k_s4d<<<(DM_*(B_/2))/4, 128>>>(D_skip, ln_g, ln_b, i, prev);
        dim3 g3(LT_/128, DM_/64, B_);
        k_gemm_mma<<<g3, 256, sizeof(SmemG)>>>(conv_b, ln_g, ln_b, i, prev);
    }
    dim3 g5(L_/8, B_);
    k_final<<<g5, 256>>>(W_pa, b_pa, W_ps, b_ps, ln_g, ln_b, (float*)d_out);
}

// round 11
// speedup vs baseline: 1.1887x; 1.0400x over previous
#include <cuda_runtime.h>
#include <cuda_fp16.h>
#include <math.h>
#include <stdint.h>

#define B_  32
#define L_  512
#define SD_ 17
#define AD_ 6
#define DM_ 384
#define NL_ 12
#define N2_ 32
#define LT_ 2048           // 4*L
#define EPS_ 1e-5f

typedef unsigned long long u64;

// ---------------- scratch (device globals; no allocations allowed) -------------
__device__ float  g_z  [B_*DM_*LT_];    // embed output (layer-0 input)
__device__ float  g_zt [B_*DM_*LT_];    // raw residual stream (pre-LN), in-place
__device__ __half g_xh [B_*DM_*LT_];    // gelu output, fp16
__device__ __half g_wh [NL_*768*DM_];   // conv_w fp16 hi
__device__ __half g_wl [NL_*768*DM_];   // conv_w fp16 lo
__device__ float2 g_lam[NL_*DM_*N2_];
__device__ float2 g_cm [NL_*DM_*N2_];
__device__ float  g_sum[B_*LT_];        // LN partial sums (reset by last CTA)
__device__ float  g_sq [B_*LT_];
__device__ float  g_m  [B_*LT_];        // LN mean
__device__ float  g_r  [B_*LT_];        // LN rstd
__device__ int    g_cnt[B_*16];         // per-(b, l-tile) arrival counters

__device__ __forceinline__ uint32_t smem_u32(const void* p) {
    uint32_t a;
    asm("{ .reg .u64 t; cvta.to.shared.u64 t, %1; cvt.u32.u64 %0, t; }" : "=r"(a) : "l"(p));
    return a;
}
__device__ __forceinline__ void cpa16(uint32_t dst, const void* src) {
    asm volatile("cp.async.cg.shared.global [%0], [%1], 16;" :: "r"(dst), "l"(src) : "memory");
}
// ---- packed f32x2 helpers ----
__device__ __forceinline__ u64 pk2(float x, float y) {
    u64 r; asm("mov.b64 %0, {%1,%2};" : "=l"(r) : "f"(x), "f"(y)); return r;
}
__device__ __forceinline__ void upk2(u64 v, float& x, float& y) {
    asm("mov.b64 {%0,%1}, %2;" : "=f"(x), "=f"(y) : "l"(v));
}
__device__ __forceinline__ u64 fma2_(u64 a, u64 b, u64 c) {
    u64 d; asm("fma.rn.f32x2 %0, %1, %2, %3;" : "=l"(d) : "l"(a), "l"(b), "l"(c)); return d;
}
__device__ __forceinline__ u64 mul2_(u64 a, u64 b) {
    u64 d; asm("mul.rn.f32x2 %0, %1, %2;" : "=l"(d) : "l"(a), "l"(b)); return d;
}
__device__ __forceinline__ u64 add2_(u64 a, u64 b) {
    u64 d; asm("add.rn.f32x2 %0, %1, %2;" : "=l"(d) : "l"(a), "l"(b)); return d;
}

// ---------------- K0: per-layer S4D coefficient precompute ---------------------
__global__ void k_precompute(const float* __restrict__ log_dt,
                             const float* __restrict__ C_ri,
                             const float* __restrict__ log_A_real,
                             const float* __restrict__ A_imag) {
    int idx = blockIdx.x * blockDim.x + threadIdx.x;
    if (idx >= NL_*DM_*N2_) return;
    int h = (idx / N2_) % DM_;
    int i = idx / (N2_*DM_);
    float dt = expf(log_dt[i*DM_ + h]);
    float Ar = -expf(log_A_real[idx]);
    float Ai = A_imag[idx];
    float dr = Ar*dt, di = Ai*dt;
    float er = expf(dr);
    float lr = er*cosf(di), li = er*sinf(di);
    float exr = lr - 1.0f, exi = li;
    float den = Ar*Ar + Ai*Ai;
    float wr = (exr*Ar + exi*Ai)/den;
    float wi = (exi*Ar - exr*Ai)/den;
    float Cr = C_ri[idx*2+0], Ci = C_ri[idx*2+1];
    g_lam[idx] = make_float2(lr, li);
    g_cm[idx]  = make_float2(2.0f*(Cr*wr - Ci*wi), 2.0f*(Cr*wi + Ci*wr));
}

// ---------------- K0b: weight split fp32 -> fp16 hi/lo -------------------------
__global__ void k_prep_w(const float* __restrict__ conv_w) {
    int idx = blockIdx.x * blockDim.x + threadIdx.x;
    if (idx >= NL_*768*DM_) return;
    float v = conv_w[idx];
    __half h = __float2half_rn(v);
    g_wh[idx] = h;
    g_wl[idx] = __float2half_rn(v - __half2float(h));
}

// ---------------- K1: embedding + interleave into (B, DM, 4L) ------------------
__global__ void k_embed(const float* __restrict__ states,
                        const float* __restrict__ actions,
                        const float* __restrict__ rtg,
                        const float* __restrict__ ctg,
                        const int*   __restrict__ tsteps,
                        const float* __restrict__ W_es, const float* __restrict__ b_es,
                        const float* __restrict__ W_ea, const float* __restrict__ b_ea,
                        const float* __restrict__ W_er, const float* __restrict__ b_er,
                        const float* __restrict__ W_ec, const float* __restrict__ b_ec,
                        const float* __restrict__ E_t) {
    int bl = blockIdx.x;
    int b = bl / L_, l = bl % L_;
    int h = threadIdx.x;
    int t = tsteps[bl];
    float te = E_t[t*DM_ + h];
    float r = rtg[bl], c = ctg[bl];
    float er = fmaf(r, W_er[h], b_er[h]) + te;
    float ec = fmaf(c, W_ec[h], b_ec[h]) + te;
    float es = b_es[h] + te;
    #pragma unroll
    for (int s = 0; s < SD_; s++) es = fmaf(states[bl*SD_ + s], W_es[s*DM_ + h], es);
    float ea = b_ea[h] + te;
    #pragma unroll
    for (int s = 0; s < AD_; s++) ea = fmaf(actions[bl*AD_ + s], W_ea[s*DM_ + h], ea);
    float* zr = g_z + ((size_t)(b*DM_ + h))*LT_ + 4*l;
    zr[0] = er; zr[1] = ec; zr[2] = es; zr[3] = ea;
}

// ---------------- K2: S4D recurrence, 2 batch-streams/lane via f32x2 -----------
__global__ __launch_bounds__(128) void k_s4d(const float* __restrict__ Dskip,
                                             const float* __restrict__ ln_g,
                                             const float* __restrict__ ln_b,
                                             int layer, int prev) {
    __shared__ __align__(16) u64 buf[4][32][34];   // [t][n + 2 pad]
    __shared__ __align__(16) u64 zs [4][32];
    int wid  = threadIdx.x >> 5;
    int lane = threadIdx.x & 31;
    int gw = blockIdx.x*4 + wid;
    int h  = gw % DM_;
    int bq = gw / DM_;
    int b0 = bq*2, b1 = bq*2 + 1;
    int pidx = (layer*DM_ + h)*N2_ + lane;
    float2 LM = g_lam[pidx];
    float2 CM = g_cm[pidx];
    u64 LMx2  = pk2( LM.x,  LM.x);
    u64 LMy2  = pk2( LM.y,  LM.y);
    u64 nLMy2 = pk2(-LM.y, -LM.y);
    u64 CMx2  = pk2( CM.x,  CM.x);
    u64 nCMy2 = pk2(-CM.y, -CM.y);
    float D   = Dskip[layer*DM_ + h];
    float lng = 1.0f, lnb = 0.0f;
    const float* zsrc = prev ? g_zt : g_z;
    if (prev) { lng = ln_g[(layer-1)*DM_ + h]; lnb = ln_b[(layer-1)*DM_ + h]; }
    const float* z0r = zsrc + ((size_t)(b0*DM_ + h))*LT_;
    const float* z1r = zsrc + ((size_t)(b1*DM_ + h))*LT_;
    const float* m0r = g_m + (size_t)b0*LT_;
    const float* m1r = g_m + (size_t)b1*LT_;
    const float* r0r = g_r + (size_t)b0*LT_;
    const float* r1r = g_r + (size_t)b1*LT_;
    __half* xh0 = g_xh + ((size_t)(b0*DM_ + h))*LT_;
    __half* xh1 = g_xh + ((size_t)(b1*DM_ + h))*LT_;

    u64 sr = 0ULL, si = 0ULL;
    u64 (*bw)[34] = buf[wid];
    u64* zw = zs[wid];
    for (int lb = 0; lb < LT_; lb += 32) {
        int l = lb + lane;
        float z0 = z0r[l], z1 = z1r[l];
        if (prev) {
            z0 = fmaf((z0 - m0r[l]) * r0r[l], lng, lnb);
            z1 = fmaf((z1 - m1r[l]) * r1r[l], lng, lnb);
        }
        zw[lane] = pk2(z0, z1);
        __syncwarp();
        #pragma unroll
        for (int t = 0; t < 32; t += 2) {
            ulonglong2 zz = *(const ulonglong2*)&zw[t];
            u64 nsr = fma2_(LMx2, sr, fma2_(nLMy2, si, zz.x));
            u64 nsi = fma2_(LMy2, sr, mul2_(LMx2, si));
            sr = nsr; si = nsi;
            bw[t][lane] = fma2_(CMx2, sr, mul2_(nCMy2, si));
            nsr = fma2_(LMx2, sr, fma2_(nLMy2, si, zz.y));
            nsi = fma2_(LMy2, sr, mul2_(LMx2, si));
            sr = nsr; si = nsi;
            bw[t+1][lane] = fma2_(CMx2, sr, mul2_(nCMy2, si));
        }
        __syncwarp();
        u64 a0 = 0ULL, a1 = 0ULL, a2 = 0ULL, a3 = 0ULL;
        #pragma unroll
        for (int k = 0; k < 8; k++) {
            ulonglong2 v0 = *(const ulonglong2*)&bw[lane][k*4    ];
            ulonglong2 v1 = *(const ulonglong2*)&bw[lane][k*4 + 2];
            a0 = add2_(a0, v0.x);
            a1 = add2_(a1, v0.y);
            a2 = add2_(a2, v1.x);
            a3 = add2_(a3, v1.y);
        }
        u64 acc = add2_(add2_(a0, a1), add2_(a2, a3));
        float y0, y1;
        upk2(acc, y0, y1);
        float yv0 = fmaf(D, z0, y0);
        float yv1 = fmaf(D, z1, y1);
        float ge0 = 0.5f * yv0 * (1.0f + erff(yv0 * 0.70710678118654752f));
        float ge1 = 0.5f * yv1 * (1.0f + erff(yv1 * 0.70710678118654752f));
        xh0[l] = __float2half_rn(ge0);
        xh1[l] = __float2half_rn(ge1);
        __syncwarp();
    }
}

// ---------------- K3: 2-term mma.sync GEMM + GLU + residual + LN stats ---------
// D = (w_hi + w_lo) * x_fp16, 3-stage cp.async ring, RAW-spaced MMA order.
#define BK_ 32
#define AP_ 40
#define BP_ 136
#define NCH_ (DM_/BK_)   // 12

struct Buf {
    __half aa_hi[64][AP_], aa_lo[64][AP_];
    __half ag_hi[64][AP_], ag_lo[64][AP_];
    __half bhi[BK_][BP_];
};
struct Epi {
    float gbuf[64][132];
    float st_s[128][16];
    float st_q[128][16];
};
struct SmemG {
    union { Buf buf[3]; Epi ep; };
};

__device__ __forceinline__ void ldmx4(uint32_t* r, uint32_t addr) {
    asm volatile("ldmatrix.sync.aligned.m8n8.x4.shared.b16 {%0,%1,%2,%3}, [%4];"
        : "=r"(r[0]), "=r"(r[1]), "=r"(r[2]), "=r"(r[3]) : "r"(addr));
}
__device__ __forceinline__ void ldmx4t(uint32_t* r, uint32_t addr) {
    asm volatile("ldmatrix.sync.aligned.m8n8.x4.trans.shared.b16 {%0,%1,%2,%3}, [%4];"
        : "=r"(r[0]), "=r"(r[1]), "=r"(r[2]), "=r"(r[3]) : "r"(addr));
}
__device__ __forceinline__ void mma16816(float* c, const uint32_t* a, uint32_t b0, uint32_t b1) {
    asm volatile("mma.sync.aligned.m16n8k16.row.col.f32.f16.f16.f32 "
        "{%0,%1,%2,%3}, {%4,%5,%6,%7}, {%8,%9}, {%0,%1,%2,%3};"
        : "+f"(c[0]), "+f"(c[1]), "+f"(c[2]), "+f"(c[3])
        : "r"(a[0]), "r"(a[1]), "r"(a[2]), "r"(a[3]), "r"(b0), "r"(b1));
}

__device__ __forceinline__ void load_chunk(Buf* bf, const __half* whL, const __half* wlL,
                                           const __half* xhB, int o0, int k0, int tid) {
    int row = tid >> 2, q = (tid & 3) * 8;
    size_t offA = (size_t)(o0 + row)*DM_ + k0 + q;
    size_t offG = (size_t)(384 + o0 + row)*DM_ + k0 + q;
    cpa16(smem_u32(&bf->aa_hi[row][q]), whL + offA);
    cpa16(smem_u32(&bf->aa_lo[row][q]), wlL + offA);
    cpa16(smem_u32(&bf->ag_hi[row][q]), whL + offG);
    cpa16(smem_u32(&bf->ag_lo[row][q]), wlL + offG);
    int br = tid >> 3, bq = (tid & 7) * 8;
    const __half* xh = xhB + (size_t)(k0 + br)*LT_;
    cpa16(smem_u32(&bf->bhi[br][bq     ]), xh + bq);
    cpa16(smem_u32(&bf->bhi[br][bq + 64]), xh + bq + 64);
}

__global__ __launch_bounds__(256, 2) void k_gemm_mma(const float* __restrict__ conv_b,
                                                     const float* __restrict__ ln_g,
                                                     const float* __restrict__ ln_b,
                                                     int layer, int prev) {
    extern __shared__ char dsm[];
    SmemG* sm = (SmemG*)dsm;
    __shared__ int lastflag;
    int tid = threadIdx.x;
    int l0 = blockIdx.x * 128;
    int o0 = blockIdx.y * 64;
    int b  = blockIdx.z;
    const __half* whL = g_wh + (size_t)layer*768*DM_;
    const __half* wlL = g_wl + (size_t)layer*768*DM_;
    const __half* xhB = g_xh + (size_t)b*DM_*LT_ + l0;
    const float*  cb  = conv_b + layer*768;

    int w = tid >> 5, lane = tid & 31;
    bool is_g = (w >= 4);
    int wl = w & 3;
    int m_off = (wl & 1) * 32;
    int n_off = (wl >> 1) * 64;

    float c[2][8][4];
    #pragma unroll
    for (int i = 0; i < 2; i++)
        #pragma unroll
        for (int j = 0; j < 8; j++)
            #pragma unroll
            for (int q = 0; q < 4; q++) c[i][j][q] = 0.0f;

    load_chunk(&sm->buf[0], whL, wlL, xhB, o0, 0, tid);
    asm volatile("cp.async.commit_group;" ::: "memory");
    load_chunk(&sm->buf[1], whL, wlL, xhB, o0, BK_, tid);
    asm volatile("cp.async.commit_group;" ::: "memory");

    int stage = 0;
    for (int ch = 0; ch < NCH_; ch++) {
        if (ch == NCH_ - 1) {
            asm volatile("cp.async.wait_group 0;" ::: "memory");
        } else {
            asm volatile("cp.async.wait_group 1;" ::: "memory");
        }
        __syncthreads();
        Buf* bf = &sm->buf[stage];
        const __half (*Ahi)[AP_] = is_g ? bf->ag_hi : bf->aa_hi;
        const __half (*Alo)[AP_] = is_g ? bf->ag_lo : bf->aa_lo;
        #pragma unroll
        for (int s = 0; s < 2; s++) {
            uint32_t ah[2][4], al[2][4];
            int arow = m_off + (lane & 15);
            int acol = s*16 + (lane >> 4)*8;
            #pragma unroll
            for (int mt = 0; mt < 2; mt++) {
                ldmx4 (ah[mt], smem_u32(&Ahi[arow + mt*16][acol]));
                ldmx4 (al[mt], smem_u32(&Alo[arow + mt*16][acol]));
            }
            int brow = s*16 + (lane & 15);
            #pragma unroll
            for (int g4 = 0; g4 < 4; g4++) {
                int bcol = n_off + g4*16 + (lane >> 4)*8;
                uint32_t bh[4];
                ldmx4t(bh, smem_u32(&bf->bhi[brow][bcol]));
                // hi pass over 4 distinct accumulators, then lo pass:
                // same-acc MMAs are 4 apart (no tensor RAW back-to-back),
                // per-acc order (hi before lo) preserved -> bitwise identical.
                #pragma unroll
                for (int hf = 0; hf < 2; hf++)
                    #pragma unroll
                    for (int mt = 0; mt < 2; mt++)
                        mma16816(c[mt][g4*2 + hf], ah[mt], bh[hf*2], bh[hf*2+1]);
                #pragma unroll
                for (int hf = 0; hf < 2; hf++)
                    #pragma unroll
                    for (int mt = 0; mt < 2; mt++)
                        mma16816(c[mt][g4*2 + hf], al[mt], bh[hf*2], bh[hf*2+1]);
            }
        }
        if (ch + 2 < NCH_) {
            int ns = stage + 2; if (ns >= 3) ns -= 3;
            load_chunk(&sm->buf[ns], whL, wlL, xhB, o0, (ch+2)*BK_, tid);
            asm volatile("cp.async.commit_group;" ::: "memory");
        }
        if (++stage == 3) stage = 0;
    }
    __syncthreads();   // all MMA reads done before Epi overwrites buf

    // ---- epilogue: g stash -> GLU + residual(+LN of prev) -> LN stats ----------
    if (is_g) {
        #pragma unroll
        for (int mt = 0; mt < 2; mt++)
            #pragma unroll
            for (int nt = 0; nt < 8; nt++) {
                int r  = m_off + mt*16 + (lane >> 2);
                int cc = n_off + nt*8 + (lane & 3)*2;
                *(float2*)&sm->ep.gbuf[r  ][cc] = make_float2(c[mt][nt][0], c[mt][nt][1]);
                *(float2*)&sm->ep.gbuf[r+8][cc] = make_float2(c[mt][nt][2], c[mt][nt][3]);
            }
    }
    __syncthreads();
    if (!is_g) {
        size_t bL = (size_t)b*LT_ + l0;
        const float* lngL = ln_g + (prev ? (layer-1)*DM_ : 0);
        const float* lnbL = ln_b + (prev ? (layer-1)*DM_ : 0);
        float ba[2][2], bg[2][2], lgv[2][2], lbv[2][2];
        #pragma unroll
        for (int mt = 0; mt < 2; mt++)
            #pragma unroll
            for (int rh = 0; rh < 2; rh++) {
                int o = o0 + m_off + mt*16 + (lane >> 2) + rh*8;
                ba[mt][rh] = cb[o]; bg[mt][rh] = cb[384 + o];
                lgv[mt][rh] = prev ? lngL[o] : 1.0f;
                lbv[mt][rh] = prev ? lnbL[o] : 0.0f;
            }
        int slot = (wl & 1)*8 + (lane >> 2);
        #pragma unroll
        for (int nt = 0; nt < 8; nt++) {
            int cc = n_off + nt*8 + (lane & 3)*2;
            float2 mv = make_float2(0.f, 0.f), rv = make_float2(1.f, 1.f);
            if (prev) {
                mv = *(const float2*)&g_m[bL + cc];
                rv = *(const float2*)&g_r[bL + cc];
            }
            float s0 = 0.f, s1 = 0.f, q0 = 0.f, q1 = 0.f;
            #pragma unroll
            for (int mt = 0; mt < 2; mt++)
                #pragma unroll
                for (int rh = 0; rh < 2; rh++) {
                    int row = m_off + mt*16 + (lane >> 2) + rh*8;
                    int o   = o0 + row;
                    float2 gv = *(float2*)&sm->ep.gbuf[row][cc];
                    size_t gix = ((size_t)(b*DM_ + o))*LT_ + l0 + cc;
                    float2 res;
                    if (prev) {
                        float2 raw = *(const float2*)&g_zt[gix];
                        res.x = fmaf((raw.x - mv.x) * rv.x, lgv[mt][rh], lbv[mt][rh]);
                        res.y = fmaf((raw.y - mv.y) * rv.y, lgv[mt][rh], lbv[mt][rh]);
                    } else {
                        res = *(const float2*)&g_z[gix];
                    }
                    float a0 = c[mt][nt][rh*2+0] + ba[mt][rh];
                    float a1 = c[mt][nt][rh*2+1] + ba[mt][rh];
                    float g0 = gv.x + bg[mt][rh], g1 = gv.y + bg[mt][rh];
                    float sg0 = 1.0f / (1.0f + expf(-g0));
                    float sg1 = 1.0f / (1.0f + expf(-g1));
                    float v0 = fmaf(a0, sg0, res.x);
                    float v1 = fmaf(a1, sg1, res.y);
                    *(float2*)&g_zt[gix] = make_float2(v0, v1);
                    s0 += v0; q0 = fmaf(v0, v0, q0);
                    s1 += v1; q1 = fmaf(v1, v1, q1);
                }
            sm->ep.st_s[cc  ][slot] = s0;
            sm->ep.st_s[cc+1][slot] = s1;
            sm->ep.st_q[cc  ][slot] = q0;
            sm->ep.st_q[cc+1][slot] = q1;
        }
    }
    __syncthreads();
    {
        int col = tid >> 1, which = tid & 1;
        const float* arr = which ? &sm->ep.st_q[col][0] : &sm->ep.st_s[col][0];
        float s = 0.f;
        #pragma unroll
        for (int k = 0; k < 16; k++) s += arr[k];
        float* dst = which ? g_sq : g_sum;
        atomicAdd(dst + (size_t)b*LT_ + l0 + col, s);
    }
    // ---- fused stat finalize: last CTA of this (b, l-tile) computes m/rstd -----
    __threadfence();
    if (tid == 0) {
        int old = atomicAdd(&g_cnt[b*16 + blockIdx.x], 1);
        lastflag = (old == (int)gridDim.y - 1);
    }
    __syncthreads();
    if (lastflag) {
        if (tid < 128) {
            size_t ix = (size_t)b*LT_ + l0 + tid;
            float s = __ldcg(&g_sum[ix]);
            float q = __ldcg(&g_sq[ix]);
            float m = s * (1.0f/DM_);
            float v = q * (1.0f/DM_) - m*m;
            g_m[ix] = m;
            g_r[ix] = rsqrtf(v + EPS_);
            g_sum[ix] = 0.0f;
            g_sq[ix]  = 0.0f;
        } else if (tid == 128) {
            g_cnt[b*16 + blockIdx.x] = 0;
        }
    }
}

// ---------------- K5: output projections (normalize final z on the fly) --------
__global__ __launch_bounds__(256) void k_final(const float* __restrict__ W_pa,
                                               const float* __restrict__ b_pa,
                                               const float* __restrict__ W_ps,
                                               const float* __restrict__ b_ps,
                                               const float* __restrict__ ln_g,
                                               const float* __restrict__ ln_b,
                                               float* __restrict__ out) {
    __shared__ float zt[DM_][32];
    int b  = blockIdx.y;
    int l0 = blockIdx.x * 8;
    int p  = threadIdx.x & 31;
    int hg = threadIdx.x >> 5;
    size_t base = (size_t)b*LT_ + l0*4;
    float m = g_m[base + p];
    float r = g_r[base + p];
    const float* lg = ln_g + (NL_-1)*DM_;
    const float* lb = ln_b + (NL_-1)*DM_;
    for (int h = hg; h < DM_; h += 8) {
        float v = g_zt[((size_t)(b*DM_ + h))*LT_ + l0*4 + p];
        zt[h][p] = fmaf((v - m) * r, lg[h], lb[h]);
    }
    __syncthreads();
    int t = threadIdx.x;
    if (t < 8*(SD_ + AD_)) {
        int li = t / (SD_ + AD_);
        int o  = t % (SD_ + AD_);
        int l  = l0 + li;
        if (o < SD_) {
            int pp = li*4 + 3;
            float acc = b_ps[o];
            #pragma unroll 8
            for (int h = 0; h < DM_; h++) acc = fmaf(zt[h][pp], W_ps[h*SD_ + o], acc);
            out[((size_t)(b*L_ + l))*SD_ + o] = acc;
        } else {
            int o2 = o - SD_;
            int pp = li*4 + 2;
            float acc = b_pa[o2];
            #pragma unroll 8
            for (int h = 0; h < DM_; h++) acc = fmaf(zt[h][pp], W_pa[h*AD_ + o2], acc);
            out[(size_t)B_*L_*SD_ + ((size_t)(b*L_ + l))*AD_ + o2] = acc;
        }
    }
}

// ---------------- launch --------------------------------------------------------
extern "C" void kernel_launch(void* const* d_in, const int* in_sizes, int n_in,
                              void* d_out, int out_size) {
    const float* states     = (const float*)d_in[0];
    const float* actions    = (const float*)d_in[1];
    const float* rtg        = (const float*)d_in[2];
    const float* ctg        = (const float*)d_in[3];
    const int*   tsteps     = (const int*  )d_in[4];
    const float* W_es       = (const float*)d_in[5];
    const float* b_es       = (const float*)d_in[6];
    const float* W_ea       = (const float*)d_in[7];
    const float* b_ea       = (const float*)d_in[8];
    const float* W_er       = (const float*)d_in[9];
    const float* b_er       = (const float*)d_in[10];
    const float* W_ec       = (const float*)d_in[11];
    const float* b_ec       = (const float*)d_in[12];
    const float* E_t        = (const float*)d_in[13];
    const float* log_dt     = (const float*)d_in[14];
    const float* C_ri       = (const float*)d_in[15];
    const float* log_A_real = (const float*)d_in[16];
    const float* A_imag     = (const float*)d_in[17];
    const float* D_skip     = (const float*)d_in[18];
    const float* conv_w     = (const float*)d_in[19];
    const float* conv_b     = (const float*)d_in[20];
    const float* ln_g       = (const float*)d_in[21];
    const float* ln_b       = (const float*)d_in[22];
    const float* W_pa       = (const float*)d_in[23];
    const float* b_pa       = (const float*)d_in[24];
    const float* W_ps       = (const float*)d_in[25];
    const float* b_ps       = (const float*)d_in[26];

    cudaFuncSetAttribute(k_gemm_mma, cudaFuncAttributeMaxDynamicSharedMemorySize,
                         (int)sizeof(SmemG));

    k_precompute<<<(NL_*DM_*N2_ + 255)/256, 256>>>(log_dt, C_ri, log_A_real, A_imag);
    k_prep_w<<<(NL_*768*DM_ + 255)/256, 256>>>(conv_w);
    k_embed<<<B_*L_, DM_>>>(states, actions, rtg, ctg, tsteps,
                            W_es, b_es, W_ea, b_ea, W_er, b_er, W_ec, b_ec, E_t);
    for (int i = 0; i < NL_; i++) {
        int prev = (i > 0) ? 1 : 0;
        k_s4d<<<(DM_*(B_/2))/4, 128>>>(D_skip, ln_g, ln_b, i, prev);
        dim3 g3(LT_/128, DM_/64, B_);
        k_gemm_mma<<<g3, 256, sizeof(SmemG)>>>(conv_b, ln_g, ln_b, i, prev);
    }
    dim3 g5(L_/8, B_);
    k_final<<<g5, 256>>>(W_pa, b_pa, W_ps, b_ps, ln_g, ln_b, (float*)d_out);
}